// round 15
// baseline (speedup 1.0000x reference)
#include <cuda_runtime.h>
#include <cuda_bf16.h>
#include <math.h>
#include <stdint.h>

#define EPS_BN 1e-5f
#define EPS_LN 1e-5f
#define NQ   1024
#define NTOT 1048

// ======================= helpers =======================
__device__ __forceinline__ uint32_t smem_u32(const void* p) {
    uint32_t a;
    asm("{ .reg .u64 t; cvta.to.shared.u64 t, %1; cvt.u32.u64 %0, t; }" : "=r"(a) : "l"(p));
    return a;
}
__device__ __forceinline__ void ldsm4(uint32_t* r, uint32_t addr) {
    asm volatile("ldmatrix.sync.aligned.m8n8.x4.shared.b16 {%0,%1,%2,%3}, [%4];"
                 : "=r"(r[0]), "=r"(r[1]), "=r"(r[2]), "=r"(r[3]) : "r"(addr) : "memory");
}
__device__ __forceinline__ void mma16816(float* d, const uint32_t* a, uint32_t b0, uint32_t b1) {
    asm volatile("mma.sync.aligned.m16n8k16.row.col.f32.bf16.bf16.f32 "
                 "{%0,%1,%2,%3}, {%4,%5,%6,%7}, {%8,%9}, {%0,%1,%2,%3};"
                 : "+f"(d[0]), "+f"(d[1]), "+f"(d[2]), "+f"(d[3])
                 : "r"(a[0]), "r"(a[1]), "r"(a[2]), "r"(a[3]), "r"(b0), "r"(b1));
}
__device__ __forceinline__ float bnlr(float x, float sc, float sh) {
    x = fmaf(x, sc, sh);
    return x > 0.f ? x : 0.2f * x;
}

// ======================= scratch (NHWC) =======================
static __device__ float g_c1out[429260800];   // xpool1 [1048][80][40][64]
static __device__ float g_c2out[107315200];   // xpool2 [1048][40][20][64]
static __device__ float g_c3out[26828800];    // xpool3 [1048][20][10][64]
static __device__ float g_c4out[6707200];     // maxraw [1048][64]
static __device__ unsigned short g_inhi[107315200];
static __device__ unsigned short g_inlo[107315200];
static __device__ float g_stats[2048];        // 4 layers x (group,oc) x {sum,sq}
static __device__ __align__(16) unsigned short g_wF1[4096];
static __device__ __align__(16) unsigned short g_wF2[73728];
static __device__ __align__(16) unsigned short g_wF3[73728];
static __device__ __align__(16) unsigned short g_wF4[73728];
static __device__ float g_emb[NTOT * 64];
static __device__ float g_sn[3 * 64];

__device__ __forceinline__ int bn_group(int n) { return (n < NQ) ? 0 : (1 + ((n - NQ) >> 3)); }

__device__ __forceinline__ void stats_flush(int base, int n, int lane, int warp_n,
                                            float* s0, float* s1, float* q0, float* q1) {
#pragma unroll
    for (int o = 4; o <= 16; o <<= 1) {
#pragma unroll
        for (int nb = 0; nb < 4; nb++) {
            s0[nb] += __shfl_down_sync(0xffffffffu, s0[nb], o);
            s1[nb] += __shfl_down_sync(0xffffffffu, s1[nb], o);
            q0[nb] += __shfl_down_sync(0xffffffffu, q0[nb], o);
            q1[nb] += __shfl_down_sync(0xffffffffu, q1[nb], o);
        }
    }
    if (lane < 4) {
        int g = bn_group(n);
#pragma unroll
        for (int nb = 0; nb < 4; nb++) {
            int c0 = warp_n * 32 + nb * 8 + lane * 2;
            atomicAdd(&g_stats[base + (g * 64 + c0) * 2],     s0[nb]);
            atomicAdd(&g_stats[base + (g * 64 + c0) * 2 + 1], q0[nb]);
            atomicAdd(&g_stats[base + (g * 64 + c0 + 1) * 2],     s1[nb]);
            atomicAdd(&g_stats[base + (g * 64 + c0 + 1) * 2 + 1], q1[nb]);
        }
    }
}

// ======================= launch 1: ALL weight prep + stats zero =======================
__global__ void prep_k(const float* __restrict__ w1, const float* __restrict__ w2,
                       const float* __restrict__ w3, const float* __restrict__ w4) {
    int y = blockIdx.y;
    int e = blockIdx.x * 256 + threadIdx.x;
    if (y == 0) {
        if (e < 2048) g_stats[e] = 0.f;
        if (e >= 1024) return;
        int nb = e & 7, lane = (e >> 3) & 31, kk = (e >> 8) & 1, cmb = (e >> 9) & 1;
        int n = nb * 8 + (lane >> 2);
#pragma unroll
        for (int j = 0; j < 2; j++)
#pragma unroll
            for (int h = 0; h < 2; h++) {
                int k = kk * 16 + (lane & 3) * 2 + j * 8 + h;
                float x = 0.f;
                if (k < 27) { int ic = k / 9, s = k - ic * 9; x = w1[(n * 3 + ic) * 9 + s]; }
                __nv_bfloat16 hi = __float2bfloat16(x);
                unsigned short v;
                if (cmb == 0) v = __bfloat16_as_ushort(hi);
                else          v = __bfloat16_as_ushort(__float2bfloat16(x - __bfloat162float(hi)));
                g_wF1[e * 4 + j * 2 + h] = v;
            }
    } else {
        if (e >= 18432) return;
        const float* w = (y == 1) ? w2 : (y == 2) ? w3 : w4;
        unsigned short* dst = (y == 1) ? g_wF2 : (y == 2) ? g_wF3 : g_wF4;
        int nb = e & 7, lane = (e >> 3) & 31, kk = (e >> 8) & 3, cmb = (e >> 10) & 1, s = e >> 11;
        int n = nb * 8 + (lane >> 2);
#pragma unroll
        for (int j = 0; j < 2; j++)
#pragma unroll
            for (int h = 0; h < 2; h++) {
                int k = kk * 16 + (lane & 3) * 2 + j * 8 + h;
                float x = w[(n * 64 + k) * 9 + s];
                __nv_bfloat16 hi = __float2bfloat16(x);
                unsigned short v;
                if (cmb == 0) v = __bfloat16_as_ushort(hi);
                else          v = __bfloat16_as_ushort(__float2bfloat16(x - __bfloat162float(hi)));
                dst[e * 4 + j * 2 + h] = v;
            }
    }
}

// ===== launch 2: L1 mma conv, SMEM image, DOUBLE-BUFFERED A, one sync/tile =====
__global__ void __launch_bounds__(256, 2) conv1_t(
    const float* __restrict__ in1, const float* __restrict__ in2,
    const unsigned short* __restrict__ wF)
{
    constexpr int H = 80, NT = 50;
    extern __shared__ __align__(16) unsigned char dsm[];
    unsigned char* sA0 = dsm;                        // 2 x 16384 B A tiles
    float* sraw = (float*)(dsm + 32768);             // 19200 floats
    const uint32_t sb0 = smem_u32(sA0);
    const int tid = threadIdx.x, lane = tid & 31, wid = tid >> 5;
    const int warp_m = wid & 3, warp_n = wid >> 2;
    const int khalf = lane >> 4;
    const int n = blockIdx.x;
    const float* gin = (n < NQ) ? in1 + (size_t)n * 19200 : in2 + (size_t)(n - NQ) * 19200;
    float* xp = g_c1out + (size_t)n * (80 * 40 * 64);

    for (int i = tid; i < 4800; i += 256)
        reinterpret_cast<float4*>(sraw)[i] = reinterpret_cast<const float4*>(gin)[i];

    const int p = tid & 127, kh = tid >> 7;          // warp-uniform kh
    float s0[4] = {0,0,0,0}, s1[4] = {0,0,0,0}, q0[4] = {0,0,0,0}, q1[4] = {0,0,0,0};
    uint32_t hp[8], lp[8];
    __syncthreads();

#define TAP(k, j) { \
    float val = 0.f; \
    if ((k) < 27) { \
        constexpr int ic = (k) / 9, s9 = (k) - ic * 9; \
        constexpr int dy = s9 / 3 - 1, dx = s9 % 3 - 1; \
        int yy = y + dy, xx = x + dx; \
        if ((unsigned)yy < (unsigned)H && (unsigned)xx < (unsigned)H) \
            val = sraw[ic * 6400 + yy * H + xx]; \
    } \
    __nv_bfloat16 hb = __float2bfloat16(val); \
    uint32_t hv = __bfloat16_as_ushort(hb); \
    uint32_t lv = __bfloat16_as_ushort(__float2bfloat16(val - __bfloat162float(hb))); \
    if (((j) & 1) == 0) { hp[(j) >> 1] = hv; lp[(j) >> 1] = lv; } \
    else { hp[(j) >> 1] |= hv << 16; lp[(j) >> 1] |= lv << 16; } }

#define GATHER(tt) { \
    int P = (tt) * 128 + p; \
    int y = P / H, x = P - (P / H) * H; \
    if (kh == 0) { \
        TAP(0,0) TAP(1,1) TAP(2,2) TAP(3,3) TAP(4,4) TAP(5,5) TAP(6,6) TAP(7,7) \
        TAP(8,8) TAP(9,9) TAP(10,10) TAP(11,11) TAP(12,12) TAP(13,13) TAP(14,14) TAP(15,15) \
    } else { \
        TAP(16,0) TAP(17,1) TAP(18,2) TAP(19,3) TAP(20,4) TAP(21,5) TAP(22,6) TAP(23,7) \
        TAP(24,8) TAP(25,9) TAP(26,10) TAP(27,11) TAP(28,12) TAP(29,13) TAP(30,14) TAP(31,15) \
    } }

#define STSFLUSH(bi) { \
    unsigned char* bb = sA0 + (bi) * 16384; \
    const uint32_t row = (uint32_t)p * 128; \
    const uint32_t sw = (uint32_t)(p & 7); \
    const uint32_t c0 = (uint32_t)(kh * 2); \
    *reinterpret_cast<uint4*>(bb + row + (((c0    ) ^ sw) << 4)) = make_uint4(hp[0], hp[1], hp[2], hp[3]); \
    *reinterpret_cast<uint4*>(bb + row + (((c0 + 1) ^ sw) << 4)) = make_uint4(hp[4], hp[5], hp[6], hp[7]); \
    *reinterpret_cast<uint4*>(bb + row + (((c0 + 4) ^ sw) << 4)) = make_uint4(lp[0], lp[1], lp[2], lp[3]); \
    *reinterpret_cast<uint4*>(bb + row + (((c0 + 5) ^ sw) << 4)) = make_uint4(lp[4], lp[5], lp[6], lp[7]); }

    GATHER(0);
    STSFLUSH(0);
    __syncthreads();

    for (int t = 0; t < NT; t++) {
        if (t + 1 < NT) GATHER(t + 1);    // LDS from sraw, overlaps mma below

        const uint32_t sbt = sb0 + (uint32_t)((t & 1) * 16384);
        float acc[2][4][4];
#pragma unroll
        for (int a = 0; a < 2; a++)
#pragma unroll
            for (int b = 0; b < 4; b++)
#pragma unroll
                for (int c = 0; c < 4; c++) acc[a][b][c] = 0.f;

        const int r0 = warp_m * 32 + (lane & 15);
        const int r1 = r0 + 16;
#pragma unroll
        for (int kk = 0; kk < 2; kk++) {
            const int chh = kk * 2 + khalf, chl = chh + 4;
            uint32_t ah0[4], ah1[4], al0[4], al1[4];
            ldsm4(ah0, sbt + (uint32_t)r0 * 128 + ((chh ^ (r0 & 7)) << 4));
            ldsm4(ah1, sbt + (uint32_t)r1 * 128 + ((chh ^ (r1 & 7)) << 4));
            ldsm4(al0, sbt + (uint32_t)r0 * 128 + ((chl ^ (r0 & 7)) << 4));
            ldsm4(al1, sbt + (uint32_t)r1 * 128 + ((chl ^ (r1 & 7)) << 4));

            const unsigned short* bs0 = wF + (((0 + kk) * 32 + lane) * 32 + warp_n * 16);
            const unsigned short* bs1 = wF + (((2 + kk) * 32 + lane) * 32 + warp_n * 16);
            uint4 h0 = *reinterpret_cast<const uint4*>(bs0);
            uint4 h1 = *reinterpret_cast<const uint4*>(bs0 + 8);
            uint4 l0 = *reinterpret_cast<const uint4*>(bs1);
            uint4 l1 = *reinterpret_cast<const uint4*>(bs1 + 8);
            uint32_t bh[8] = {h0.x, h0.y, h0.z, h0.w, h1.x, h1.y, h1.z, h1.w};
            uint32_t bl[8] = {l0.x, l0.y, l0.z, l0.w, l1.x, l1.y, l1.z, l1.w};

#pragma unroll
            for (int nb = 0; nb < 4; nb++) {
                mma16816(acc[0][nb], ah0, bh[nb * 2], bh[nb * 2 + 1]);
                mma16816(acc[1][nb], ah1, bh[nb * 2], bh[nb * 2 + 1]);
            }
#pragma unroll
            for (int nb = 0; nb < 4; nb++) {
                mma16816(acc[0][nb], ah0, bl[nb * 2], bl[nb * 2 + 1]);
                mma16816(acc[1][nb], ah1, bl[nb * 2], bl[nb * 2 + 1]);
            }
#pragma unroll
            for (int nb = 0; nb < 4; nb++) {
                mma16816(acc[0][nb], al0, bh[nb * 2], bh[nb * 2 + 1]);
                mma16816(acc[1][nb], al1, bh[nb * 2], bh[nb * 2 + 1]);
            }
        }

#pragma unroll
        for (int mb = 0; mb < 2; mb++) {
            const int rbase = t * 128 + warp_m * 32 + mb * 16;
#pragma unroll
            for (int nb = 0; nb < 4; nb++) {
                float* d = acc[mb][nb];
                s0[nb] += d[0] + d[2];
                s1[nb] += d[1] + d[3];
                q0[nb] += d[0] * d[0] + d[2] * d[2];
                q1[nb] += d[1] * d[1] + d[3] * d[3];
                float m0v = fmaxf(d[0], __shfl_xor_sync(0xffffffffu, d[0], 4));
                float m1v = fmaxf(d[1], __shfl_xor_sync(0xffffffffu, d[1], 4));
                float m2v = fmaxf(d[2], __shfl_xor_sync(0xffffffffu, d[2], 4));
                float m3v = fmaxf(d[3], __shfl_xor_sync(0xffffffffu, d[3], 4));
                if ((lane & 4) == 0) {
                    const int col = warp_n * 32 + nb * 8 + (lane & 3) * 2;
                    int P = rbase + (lane >> 2);
                    int y = P / 80, x2 = (P % 80) >> 1;
                    *reinterpret_cast<float2*>(xp + ((size_t)y * 40 + x2) * 64 + col) =
                        make_float2(m0v, m1v);
                    int P8 = P + 8;
                    int y8 = P8 / 80, x28 = (P8 % 80) >> 1;
                    *reinterpret_cast<float2*>(xp + ((size_t)y8 * 40 + x28) * 64 + col) =
                        make_float2(m2v, m3v);
                }
            }
        }

        if (t + 1 < NT) STSFLUSH((t + 1) & 1);
        __syncthreads();
    }
#undef TAP
#undef GATHER
#undef STSFLUSH
    stats_flush(0, n, lane, warp_n, s0, s1, q0, q1);
}

// ========= ypoolF: fused BN-finalize + y-pool + BN + LReLU -> bf16 hi/lo =========
template <int HO>
__global__ void ypoolF_k(const float* __restrict__ xp,
                         unsigned short* __restrict__ ohi, unsigned short* __restrict__ olo,
                         int statsBase, const float* __restrict__ gam, const float* __restrict__ bet) {
    __shared__ float s_sc[256], s_sh[256];
    {
        int t = threadIdx.x, grp = t >> 6, oc = t & 63;
        float cnt = (grp == 0 ? (float)NQ : 8.f) * (float)(4 * HO * HO);
        float m = g_stats[statsBase + t * 2] / cnt;
        float v = g_stats[statsBase + t * 2 + 1] / cnt - m * m;
        float sc = gam[oc] * rsqrtf(v + EPS_BN);
        s_sc[t] = sc;
        s_sh[t] = bet[oc] - m * sc;
    }
    __syncthreads();
    int idx = blockIdx.x * 256 + threadIdx.x;
    if (idx >= NTOT * HO * HO * 16) return;
    int c4 = idx & 15, t = idx >> 4;
    int px = t % HO; t /= HO;
    int py = t % HO;
    int n = t / HO, g = bn_group(n);
    float4 sc = *reinterpret_cast<const float4*>(&s_sc[g * 64 + c4 * 4]);
    float4 sh = *reinterpret_cast<const float4*>(&s_sh[g * 64 + c4 * 4]);
    const float* p = xp + (((size_t)n * (2 * HO) + 2 * py) * HO + px) * 64 + c4 * 4;
    float4 a = *reinterpret_cast<const float4*>(p);
    float4 b = *reinterpret_cast<const float4*>(p + HO * 64);
    float r[4];
    r[0] = bnlr(fmaxf(a.x, b.x), sc.x, sh.x);
    r[1] = bnlr(fmaxf(a.y, b.y), sc.y, sh.y);
    r[2] = bnlr(fmaxf(a.z, b.z), sc.z, sh.z);
    r[3] = bnlr(fmaxf(a.w, b.w), sc.w, sh.w);
    unsigned short h[4], l[4];
#pragma unroll
    for (int j = 0; j < 4; j++) {
        __nv_bfloat16 hb = __float2bfloat16(r[j]);
        h[j] = __bfloat16_as_ushort(hb);
        l[j] = __bfloat16_as_ushort(__float2bfloat16(r[j] - __bfloat162float(hb)));
    }
    size_t base = (((size_t)n * HO + py) * HO + px) * 64 + c4 * 4;
    *reinterpret_cast<uint2*>(ohi + base) = make_uint2((uint32_t)h[0] | ((uint32_t)h[1] << 16),
                                                       (uint32_t)h[2] | ((uint32_t)h[3] << 16));
    *reinterpret_cast<uint2*>(olo + base) = make_uint2((uint32_t)l[0] | ((uint32_t)l[1] << 16),
                                                       (uint32_t)l[2] | ((uint32_t)l[3] << 16));
}

// ======================= conv L2-L4 + stats slice ====================
template <int H>
__global__ void __launch_bounds__(256) conv_t(
    const unsigned short* __restrict__ inhi, const unsigned short* __restrict__ inlo,
    float* __restrict__ outbuf, const unsigned short* __restrict__ wBf, int statsBase)
{
    constexpr int NPIX = H * H, W2 = H + 2;
    constexpr int NT = (NPIX + 127) / 128;
    constexpr int RB = (127 + H - 1) / H + 3;
    constexpr int SLOTS = RB * W2;
    constexpr int BANDB = SLOTS * 128;
    extern __shared__ __align__(16) unsigned char smem[];
    const uint32_t sb = smem_u32(smem);
    const int tid = threadIdx.x, lane = tid & 31, wid = tid >> 5;
    const int warp_m = wid & 3, warp_n = wid >> 2;
    const int n = blockIdx.x;
    const unsigned short* ghi = inhi + (size_t)n * NPIX * 64;
    const unsigned short* glo = inlo + (size_t)n * NPIX * 64;
    float* gout;
    if constexpr (H == 10) gout = outbuf + (size_t)n * 64;
    else                   gout = outbuf + (size_t)n * (H * (H / 2) * 64);

    float s0[4] = {0,0,0,0}, s1[4] = {0,0,0,0}, q0[4] = {0,0,0,0}, q1[4] = {0,0,0,0};

    for (int t = 0; t < NT; t++) {
        __syncthreads();
        const int m0 = t * 128, ytile = m0 / H;
        for (int sl = tid; sl < SLOTS; sl += 256) {
            int r = sl / W2, c = sl - r * W2;
            int y = ytile + r - 1, x = c - 1;
            bool v = ((unsigned)y < (unsigned)H) && ((unsigned)x < (unsigned)H);
            const uint4* sh = reinterpret_cast<const uint4*>(ghi + (size_t)(y * H + x) * 64);
            const uint4* so = reinterpret_cast<const uint4*>(glo + (size_t)(y * H + x) * 64);
#pragma unroll
            for (int ch = 0; ch < 8; ch++) {
                uint4 dh = v ? sh[ch] : make_uint4(0, 0, 0, 0);
                uint4 dl = v ? so[ch] : make_uint4(0, 0, 0, 0);
                uint32_t off = (uint32_t)sl * 128 + (uint32_t)((ch ^ (sl & 7)) << 4);
                *reinterpret_cast<uint4*>(smem + off) = dh;
                *reinterpret_cast<uint4*>(smem + BANDB + off) = dl;
            }
        }
        __syncthreads();

        int bp[2];
#pragma unroll
        for (int mb = 0; mb < 2; mb++) {
            int p = m0 + warp_m * 32 + mb * 16 + (lane & 15);
            int y = p / H, x = p - y * H;
            bp[mb] = (y - ytile + 1) * W2 + x + 1;
        }
        const int khalf = lane >> 4;

        float acc[2][4][4];
#pragma unroll
        for (int a = 0; a < 2; a++)
#pragma unroll
            for (int b = 0; b < 4; b++)
#pragma unroll
                for (int c = 0; c < 4; c++) acc[a][b][c] = 0.f;

#pragma unroll 3
        for (int s = 0; s < 9; s++) {
            const int so9 = (s / 3 - 1) * W2 + (s % 3 - 1);
            const int b0 = bp[0] + so9, b1 = bp[1] + so9;
#pragma unroll
            for (int kk = 0; kk < 4; kk++) {
                const int ch = kk * 2 + khalf;
                uint32_t off0 = (uint32_t)b0 * 128 + (uint32_t)((ch ^ (b0 & 7)) << 4);
                uint32_t off1 = (uint32_t)b1 * 128 + (uint32_t)((ch ^ (b1 & 7)) << 4);
                uint32_t ah0[4], ah1[4], al0[4], al1[4];
                ldsm4(ah0, sb + off0);
                ldsm4(ah1, sb + off1);
                ldsm4(al0, sb + BANDB + off0);
                ldsm4(al1, sb + BANDB + off1);

                const unsigned short* bs0 = wBf + ((((s * 2 + 0) * 4 + kk) * 32 + lane) * 32 + warp_n * 16);
                const unsigned short* bs1 = wBf + ((((s * 2 + 1) * 4 + kk) * 32 + lane) * 32 + warp_n * 16);
                uint4 h0 = *reinterpret_cast<const uint4*>(bs0);
                uint4 h1 = *reinterpret_cast<const uint4*>(bs0 + 8);
                uint4 l0 = *reinterpret_cast<const uint4*>(bs1);
                uint4 l1 = *reinterpret_cast<const uint4*>(bs1 + 8);
                uint32_t bh[8] = {h0.x, h0.y, h0.z, h0.w, h1.x, h1.y, h1.z, h1.w};
                uint32_t bl[8] = {l0.x, l0.y, l0.z, l0.w, l1.x, l1.y, l1.z, l1.w};

#pragma unroll
                for (int nb = 0; nb < 4; nb++) {
                    mma16816(acc[0][nb], ah0, bh[nb * 2], bh[nb * 2 + 1]);
                    mma16816(acc[1][nb], ah1, bh[nb * 2], bh[nb * 2 + 1]);
                }
#pragma unroll
                for (int nb = 0; nb < 4; nb++) {
                    mma16816(acc[0][nb], ah0, bl[nb * 2], bl[nb * 2 + 1]);
                    mma16816(acc[1][nb], ah1, bl[nb * 2], bl[nb * 2 + 1]);
                }
#pragma unroll
                for (int nb = 0; nb < 4; nb++) {
                    mma16816(acc[0][nb], al0, bh[nb * 2], bh[nb * 2 + 1]);
                    mma16816(acc[1][nb], al1, bh[nb * 2], bh[nb * 2 + 1]);
                }
            }
        }

        if constexpr (H == 10) {
            float mx0[4], mx1[4];
#pragma unroll
            for (int nb = 0; nb < 4; nb++) { mx0[nb] = -1e30f; mx1[nb] = -1e30f; }
#pragma unroll
            for (int mb = 0; mb < 2; mb++) {
                int p0 = m0 + warp_m * 32 + mb * 16 + (lane >> 2);
                bool v0 = p0 < NPIX, v1 = (p0 + 8) < NPIX;
#pragma unroll
                for (int nb = 0; nb < 4; nb++) {
                    float* d = acc[mb][nb];
                    if (v0) {
                        s0[nb] += d[0]; s1[nb] += d[1];
                        q0[nb] += d[0] * d[0]; q1[nb] += d[1] * d[1];
                        mx0[nb] = fmaxf(mx0[nb], d[0]); mx1[nb] = fmaxf(mx1[nb], d[1]);
                    }
                    if (v1) {
                        s0[nb] += d[2]; s1[nb] += d[3];
                        q0[nb] += d[2] * d[2]; q1[nb] += d[3] * d[3];
                        mx0[nb] = fmaxf(mx0[nb], d[2]); mx1[nb] = fmaxf(mx1[nb], d[3]);
                    }
                }
            }
#pragma unroll
            for (int o = 4; o <= 16; o <<= 1)
#pragma unroll
                for (int nb = 0; nb < 4; nb++) {
                    mx0[nb] = fmaxf(mx0[nb], __shfl_xor_sync(0xffffffffu, mx0[nb], o));
                    mx1[nb] = fmaxf(mx1[nb], __shfl_xor_sync(0xffffffffu, mx1[nb], o));
                }
            __syncthreads();
            float* smax = (float*)smem;
            if (lane < 4) {
#pragma unroll
                for (int nb = 0; nb < 4; nb++) {
                    int col = warp_n * 32 + nb * 8 + lane * 2;
                    smax[warp_m * 64 + col]     = mx0[nb];
                    smax[warp_m * 64 + col + 1] = mx1[nb];
                }
            }
            __syncthreads();
            if (tid < 64)
                gout[tid] = fmaxf(fmaxf(smax[tid], smax[64 + tid]),
                                  fmaxf(smax[128 + tid], smax[192 + tid]));
        } else {
#pragma unroll
            for (int mb = 0; mb < 2; mb++) {
                int p0 = m0 + warp_m * 32 + mb * 16 + (lane >> 2);
                bool v0 = p0 < NPIX, v1 = (p0 + 8) < NPIX;
#pragma unroll
                for (int nb = 0; nb < 4; nb++) {
                    float* d = acc[mb][nb];
                    if (v0) { s0[nb] += d[0]; s1[nb] += d[1]; q0[nb] += d[0]*d[0]; q1[nb] += d[1]*d[1]; }
                    if (v1) { s0[nb] += d[2]; s1[nb] += d[3]; q0[nb] += d[2]*d[2]; q1[nb] += d[3]*d[3]; }
                    float m0v = fmaxf(d[0], __shfl_xor_sync(0xffffffffu, d[0], 4));
                    float m1v = fmaxf(d[1], __shfl_xor_sync(0xffffffffu, d[1], 4));
                    float m2v = fmaxf(d[2], __shfl_xor_sync(0xffffffffu, d[2], 4));
                    float m3v = fmaxf(d[3], __shfl_xor_sync(0xffffffffu, d[3], 4));
                    if ((lane & 4) == 0) {
                        int col = warp_n * 32 + nb * 8 + (lane & 3) * 2;
                        if (v0) {
                            int y = p0 / H, x2 = (p0 % H) >> 1;
                            *reinterpret_cast<float2*>(gout + ((size_t)y * (H / 2) + x2) * 64 + col) =
                                make_float2(m0v, m1v);
                        }
                        if (v1) {
                            int p8 = p0 + 8, y = p8 / H, x2 = (p8 % H) >> 1;
                            *reinterpret_cast<float2*>(gout + ((size_t)y * (H / 2) + x2) * 64 + col) =
                                make_float2(m2v, m3v);
                        }
                    }
                }
            }
        }
    }
    stats_flush(statsBase, n, lane, warp_n, s0, s1, q0, q1);
}

// embedF: fused finalize L4 + BN + LReLU over per-image channel max
__global__ void embedF_k(const float* __restrict__ mx,
                         const float* __restrict__ gam, const float* __restrict__ bet) {
    int idx = blockIdx.x * 256 + threadIdx.x;
    if (idx >= NTOT * 64) return;
    int c = idx & 63, n = idx >> 6, g = bn_group(n);
    float cnt = (g == 0 ? (float)NQ : 8.f) * 100.f;
    float m = g_stats[1536 + (g * 64 + c) * 2] / cnt;
    float v = g_stats[1536 + (g * 64 + c) * 2 + 1] / cnt - m * m;
    float sc = gam[c] * rsqrtf(v + EPS_BN);
    float sh = bet[c] - m * sc;
    g_emb[idx] = bnlr(mx[idx], sc, sh);
}

// ======================= attention over 3 prototypes =======================
__global__ void attn_k(const float* __restrict__ wq, const float* __restrict__ wk,
                       const float* __restrict__ wv, const float* __restrict__ fcw,
                       const float* __restrict__ fcb, const float* __restrict__ lng,
                       const float* __restrict__ lnb) {
    __shared__ float P[3][64], Q[3][64], K[3][64], V[3][64], O[3][64];
    __shared__ float A[3][3], MU[3], SG[3], NR[3];
    int t = threadIdx.x;
    for (int l = 0; l < 3; l++) {
        float s = 0.f;
        for (int i = 0; i < 8; i++) s += g_emb[(NQ + l * 8 + i) * 64 + t];
        P[l][t] = s * 0.125f;
    }
    __syncthreads();
    for (int l = 0; l < 3; l++) {
        float q = 0.f, k = 0.f, v = 0.f;
        for (int d = 0; d < 64; d++) {
            float p = P[l][d];
            q += p * wq[t * 64 + d]; k += p * wk[t * 64 + d]; v += p * wv[t * 64 + d];
        }
        Q[l][t] = q; K[l][t] = k; V[l][t] = v;
    }
    __syncthreads();
    if (t < 9) {
        int qi = t / 3, ki = t % 3;
        float a = 0.f;
        for (int d = 0; d < 64; d++) a += Q[qi][d] * K[ki][d];
        A[qi][ki] = a * 0.125f;
    }
    __syncthreads();
    if (t < 3) {
        float m = fmaxf(A[t][0], fmaxf(A[t][1], A[t][2]));
        float e0 = expf(A[t][0] - m), e1 = expf(A[t][1] - m), e2 = expf(A[t][2] - m);
        float inv = 1.f / (e0 + e1 + e2);
        A[t][0] = e0 * inv; A[t][1] = e1 * inv; A[t][2] = e2 * inv;
    }
    __syncthreads();
    for (int l = 0; l < 3; l++)
        O[l][t] = A[l][0] * V[0][t] + A[l][1] * V[1][t] + A[l][2] * V[2][t];
    __syncthreads();
    for (int l = 0; l < 3; l++) {
        float o = fcb[t];
        for (int d = 0; d < 64; d++) o += O[l][d] * fcw[t * 64 + d];
        Q[l][t] = o + P[l][t];
    }
    __syncthreads();
    if (t < 3) {
        float s = 0.f, q = 0.f;
        for (int d = 0; d < 64; d++) { float x = Q[t][d]; s += x; q += x * x; }
        float m = s / 64.f;
        MU[t] = m;
        SG[t] = rsqrtf(q / 64.f - m * m + EPS_LN);
    }
    __syncthreads();
    for (int l = 0; l < 3; l++)
        K[l][t] = (Q[l][t] - MU[l]) * SG[l] * lng[t] + lnb[t];
    __syncthreads();
    if (t < 3) {
        float q = 0.f;
        for (int d = 0; d < 64; d++) q += K[t][d] * K[t][d];
        NR[t] = rsqrtf(q);
    }
    __syncthreads();
    for (int l = 0; l < 3; l++) g_sn[l * 64 + t] = K[l][t] * NR[l];
}

__global__ void cos_k(float* __restrict__ out) {
    int warp = threadIdx.x >> 5, lane = threadIdx.x & 31;
    int n = blockIdx.x * 4 + warp;
    if (n >= NQ) return;
    float v1 = g_emb[n * 64 + lane], v2 = g_emb[n * 64 + 32 + lane];
    float ss = v1 * v1 + v2 * v2;
#pragma unroll
    for (int o = 16; o > 0; o >>= 1) ss += __shfl_xor_sync(0xffffffffu, ss, o);
    float rn = rsqrtf(ss);
#pragma unroll
    for (int k = 0; k < 3; k++) {
        float d = v1 * g_sn[k * 64 + lane] + v2 * g_sn[k * 64 + 32 + lane];
#pragma unroll
        for (int o = 16; o > 0; o >>= 1) d += __shfl_xor_sync(0xffffffffu, d, o);
        if (lane == 0) out[n * 3 + k] = d * rn;
    }
}

// ======================= launch =======================
extern "C" void kernel_launch(void* const* d_in, const int* in_sizes, int n_in,
                              void* d_out, int out_size) {
    const float* input1  = (const float*)d_in[0];
    const float* input2  = (const float*)d_in[1];
    const float* conv1_w = (const float*)d_in[2];
    const float* conv2_w = (const float*)d_in[3];
    const float* conv3_w = (const float*)d_in[4];
    const float* conv4_w = (const float*)d_in[5];
    const float* bn_g[4] = {(const float*)d_in[6], (const float*)d_in[8], (const float*)d_in[10], (const float*)d_in[12]};
    const float* bn_b[4] = {(const float*)d_in[7], (const float*)d_in[9], (const float*)d_in[11], (const float*)d_in[13]};
    float* out = (float*)d_out;

    const int DS1  = 32768 + 76800;       // 109568: 2 A tiles + raw image
    const int SM40 = 2 * 7 * 42 * 128;    // 75264
    const int SM20 = 2 * 10 * 22 * 128;   // 56320
    const int SM10 = 2 * 16 * 12 * 128;   // 49152
    cudaFuncSetAttribute(conv1_t,    cudaFuncAttributeMaxDynamicSharedMemorySize, DS1);
    cudaFuncSetAttribute(conv_t<40>, cudaFuncAttributeMaxDynamicSharedMemorySize, SM40);
    cudaFuncSetAttribute(conv_t<20>, cudaFuncAttributeMaxDynamicSharedMemorySize, SM20);
    cudaFuncSetAttribute(conv_t<10>, cudaFuncAttributeMaxDynamicSharedMemorySize, SM10);

    unsigned short *wF1, *wF2, *wF3, *wF4, *ihi, *ilo;
    cudaGetSymbolAddress((void**)&wF1, g_wF1);
    cudaGetSymbolAddress((void**)&wF2, g_wF2);
    cudaGetSymbolAddress((void**)&wF3, g_wF3);
    cudaGetSymbolAddress((void**)&wF4, g_wF4);
    cudaGetSymbolAddress((void**)&ihi, g_inhi);
    cudaGetSymbolAddress((void**)&ilo, g_inlo);
    float *c1, *c2, *c3, *c4;
    cudaGetSymbolAddress((void**)&c1, g_c1out);
    cudaGetSymbolAddress((void**)&c2, g_c2out);
    cudaGetSymbolAddress((void**)&c3, g_c3out);
    cudaGetSymbolAddress((void**)&c4, g_c4out);

    // Launch order: prep(1), conv1_t(2), ypoolF40(3), conv_t<40>(4 <- profiled)
    prep_k<<<dim3(72, 4), 256>>>(conv1_w, conv2_w, conv3_w, conv4_w);
    conv1_t<<<NTOT, 256, DS1>>>(input1, input2, wF1);
    ypoolF_k<40><<<(NTOT * 40 * 40 * 16 + 255) / 256, 256>>>(c1, ihi, ilo, 0, bn_g[0], bn_b[0]);
    conv_t<40><<<NTOT, 256, SM40>>>(ihi, ilo, c2, wF2, 512);
    ypoolF_k<20><<<(NTOT * 20 * 20 * 16 + 255) / 256, 256>>>(c2, ihi, ilo, 512, bn_g[1], bn_b[1]);
    conv_t<20><<<NTOT, 256, SM20>>>(ihi, ilo, c3, wF3, 1024);
    ypoolF_k<10><<<(NTOT * 10 * 10 * 16 + 255) / 256, 256>>>(c3, ihi, ilo, 1024, bn_g[2], bn_b[2]);
    conv_t<10><<<NTOT, 256, SM10>>>(ihi, ilo, c4, wF4, 1536);
    embedF_k<<<(NTOT * 64 + 255) / 256, 256>>>(c4, bn_g[3], bn_b[3]);

    attn_k<<<1, 64>>>((const float*)d_in[14], (const float*)d_in[15], (const float*)d_in[16],
                      (const float*)d_in[17], (const float*)d_in[18],
                      (const float*)d_in[19], (const float*)d_in[20]);
    cos_k<<<256, 128>>>(out);
}

// round 16
// speedup vs baseline: 1.0495x; 1.0495x over previous
#include <cuda_runtime.h>
#include <cuda_bf16.h>
#include <math.h>
#include <stdint.h>

#define EPS_BN 1e-5f
#define EPS_LN 1e-5f
#define NQ   1024
#define NTOT 1048

// ======================= helpers =======================
__device__ __forceinline__ uint32_t smem_u32(const void* p) {
    uint32_t a;
    asm("{ .reg .u64 t; cvta.to.shared.u64 t, %1; cvt.u32.u64 %0, t; }" : "=r"(a) : "l"(p));
    return a;
}
__device__ __forceinline__ void ldsm4(uint32_t* r, uint32_t addr) {
    asm volatile("ldmatrix.sync.aligned.m8n8.x4.shared.b16 {%0,%1,%2,%3}, [%4];"
                 : "=r"(r[0]), "=r"(r[1]), "=r"(r[2]), "=r"(r[3]) : "r"(addr) : "memory");
}
__device__ __forceinline__ void mma16816(float* d, const uint32_t* a, uint32_t b0, uint32_t b1) {
    asm volatile("mma.sync.aligned.m16n8k16.row.col.f32.bf16.bf16.f32 "
                 "{%0,%1,%2,%3}, {%4,%5,%6,%7}, {%8,%9}, {%0,%1,%2,%3};"
                 : "+f"(d[0]), "+f"(d[1]), "+f"(d[2]), "+f"(d[3])
                 : "r"(a[0]), "r"(a[1]), "r"(a[2]), "r"(a[3]), "r"(b0), "r"(b1));
}
__device__ __forceinline__ float bnlr(float x, float sc, float sh) {
    x = fmaf(x, sc, sh);
    return x > 0.f ? x : 0.2f * x;
}

// ======================= scratch (NHWC) =======================
static __device__ float g_c1out[429260800];   // xpool1 [1048][80][40][64]
static __device__ float g_c2out[107315200];   // xpool2 [1048][40][20][64]
static __device__ float g_c3out[26828800];    // xpool3 [1048][20][10][64]
static __device__ float g_c4out[6707200];     // maxraw [1048][64]
static __device__ unsigned short g_inhi[107315200];
static __device__ unsigned short g_inlo[107315200];
static __device__ float g_stats[2048];        // 4 layers x (group,oc) x {sum,sq}
static __device__ __align__(16) unsigned short g_wF1[4096];
static __device__ __align__(16) unsigned short g_wF2[73728];
static __device__ __align__(16) unsigned short g_wF3[73728];
static __device__ __align__(16) unsigned short g_wF4[73728];
static __device__ float g_emb[NTOT * 64];
static __device__ float g_sn[3 * 64];

__device__ __forceinline__ int bn_group(int n) { return (n < NQ) ? 0 : (1 + ((n - NQ) >> 3)); }

__device__ __forceinline__ void stats_flush(int base, int n, int lane, int warp_n,
                                            float* s0, float* s1, float* q0, float* q1) {
#pragma unroll
    for (int o = 4; o <= 16; o <<= 1) {
#pragma unroll
        for (int nb = 0; nb < 4; nb++) {
            s0[nb] += __shfl_down_sync(0xffffffffu, s0[nb], o);
            s1[nb] += __shfl_down_sync(0xffffffffu, s1[nb], o);
            q0[nb] += __shfl_down_sync(0xffffffffu, q0[nb], o);
            q1[nb] += __shfl_down_sync(0xffffffffu, q1[nb], o);
        }
    }
    if (lane < 4) {
        int g = bn_group(n);
#pragma unroll
        for (int nb = 0; nb < 4; nb++) {
            int c0 = warp_n * 32 + nb * 8 + lane * 2;
            atomicAdd(&g_stats[base + (g * 64 + c0) * 2],     s0[nb]);
            atomicAdd(&g_stats[base + (g * 64 + c0) * 2 + 1], q0[nb]);
            atomicAdd(&g_stats[base + (g * 64 + c0 + 1) * 2],     s1[nb]);
            atomicAdd(&g_stats[base + (g * 64 + c0 + 1) * 2 + 1], q1[nb]);
        }
    }
}

// ======================= launch 1: ALL weight prep + stats zero =======================
__global__ void prep_k(const float* __restrict__ w1, const float* __restrict__ w2,
                       const float* __restrict__ w3, const float* __restrict__ w4) {
    int y = blockIdx.y;
    int e = blockIdx.x * 256 + threadIdx.x;
    if (y == 0) {
        if (e < 2048) g_stats[e] = 0.f;
        if (e >= 1024) return;
        int nb = e & 7, lane = (e >> 3) & 31, kk = (e >> 8) & 1, cmb = (e >> 9) & 1;
        int n = nb * 8 + (lane >> 2);
#pragma unroll
        for (int j = 0; j < 2; j++)
#pragma unroll
            for (int h = 0; h < 2; h++) {
                int k = kk * 16 + (lane & 3) * 2 + j * 8 + h;
                float x = 0.f;
                if (k < 27) { int ic = k / 9, s = k - ic * 9; x = w1[(n * 3 + ic) * 9 + s]; }
                __nv_bfloat16 hi = __float2bfloat16(x);
                unsigned short v;
                if (cmb == 0) v = __bfloat16_as_ushort(hi);
                else          v = __bfloat16_as_ushort(__float2bfloat16(x - __bfloat162float(hi)));
                g_wF1[e * 4 + j * 2 + h] = v;
            }
    } else {
        if (e >= 18432) return;
        const float* w = (y == 1) ? w2 : (y == 2) ? w3 : w4;
        unsigned short* dst = (y == 1) ? g_wF2 : (y == 2) ? g_wF3 : g_wF4;
        int nb = e & 7, lane = (e >> 3) & 31, kk = (e >> 8) & 3, cmb = (e >> 10) & 1, s = e >> 11;
        int n = nb * 8 + (lane >> 2);
#pragma unroll
        for (int j = 0; j < 2; j++)
#pragma unroll
            for (int h = 0; h < 2; h++) {
                int k = kk * 16 + (lane & 3) * 2 + j * 8 + h;
                float x = w[(n * 64 + k) * 9 + s];
                __nv_bfloat16 hi = __float2bfloat16(x);
                unsigned short v;
                if (cmb == 0) v = __bfloat16_as_ushort(hi);
                else          v = __bfloat16_as_ushort(__float2bfloat16(x - __bfloat162float(hi)));
                dst[e * 4 + j * 2 + h] = v;
            }
    }
}

// ===== launch 2: L1 mma conv, SMEM image, M=256 tile (2 halves per sync pair) =====
__global__ void __launch_bounds__(256, 2) conv1_t(
    const float* __restrict__ in1, const float* __restrict__ in2,
    const unsigned short* __restrict__ wF)
{
    constexpr int H = 80, NT2 = 25;               // 25 iterations x 256 px
    extern __shared__ __align__(16) unsigned char dsm[];
    unsigned char* sA = dsm;                      // 32768 B: 256 rows x 128 B
    float* sraw = (float*)(dsm + 32768);          // 19200 floats
    const uint32_t sb = smem_u32(sA);
    const int tid = threadIdx.x, lane = tid & 31, wid = tid >> 5;
    const int warp_m = wid & 3, warp_n = wid >> 2;
    const int khalf = lane >> 4;
    const int n = blockIdx.x;
    const float* gin = (n < NQ) ? in1 + (size_t)n * 19200 : in2 + (size_t)(n - NQ) * 19200;
    float* xp = g_c1out + (size_t)n * (80 * 40 * 64);

    for (int i = tid; i < 4800; i += 256)
        reinterpret_cast<float4*>(sraw)[i] = reinterpret_cast<const float4*>(gin)[i];

    float s0[4] = {0,0,0,0}, s1[4] = {0,0,0,0}, q0[4] = {0,0,0,0}, q1[4] = {0,0,0,0};
    uint32_t hp[8], lp[8];
    __syncthreads();

#define TAP(k, j) { \
    float val = 0.f; \
    if ((k) < 27) { \
        constexpr int ic = (k) / 9, s9 = (k) - ic * 9; \
        constexpr int dy = s9 / 3 - 1, dx = s9 % 3 - 1; \
        int yy = y + dy, xx = x + dx; \
        if ((unsigned)yy < (unsigned)H && (unsigned)xx < (unsigned)H) \
            val = sraw[ic * 6400 + yy * H + xx]; \
    } \
    __nv_bfloat16 hb = __float2bfloat16(val); \
    uint32_t hv = __bfloat16_as_ushort(hb); \
    uint32_t lv = __bfloat16_as_ushort(__float2bfloat16(val - __bfloat162float(hb))); \
    if (((j) & 1) == 0) { hp[(j) >> 1] = hv; lp[(j) >> 1] = lv; } \
    else { hp[(j) >> 1] |= hv << 16; lp[(j) >> 1] |= lv << 16; } }

#define STSFLUSH(c0) { \
    const uint32_t row = (uint32_t)tid * 128; \
    const uint32_t sw = (uint32_t)(tid & 7); \
    *reinterpret_cast<uint4*>(sA + row + ((((c0)    ) ^ sw) << 4)) = make_uint4(hp[0], hp[1], hp[2], hp[3]); \
    *reinterpret_cast<uint4*>(sA + row + ((((c0) + 1) ^ sw) << 4)) = make_uint4(hp[4], hp[5], hp[6], hp[7]); \
    *reinterpret_cast<uint4*>(sA + row + ((((c0) + 4) ^ sw) << 4)) = make_uint4(lp[0], lp[1], lp[2], lp[3]); \
    *reinterpret_cast<uint4*>(sA + row + ((((c0) + 5) ^ sw) << 4)) = make_uint4(lp[4], lp[5], lp[6], lp[7]); }

    for (int it = 0; it < NT2; it++) {
        // gather own row: 32 taps in 2 passes of 16 channels
        {
            int P = it * 256 + tid;
            int y = P / H, x = P - (P / H) * H;
            TAP(0,0) TAP(1,1) TAP(2,2) TAP(3,3) TAP(4,4) TAP(5,5) TAP(6,6) TAP(7,7)
            TAP(8,8) TAP(9,9) TAP(10,10) TAP(11,11) TAP(12,12) TAP(13,13) TAP(14,14) TAP(15,15)
            STSFLUSH(0)
            TAP(16,0) TAP(17,1) TAP(18,2) TAP(19,3) TAP(20,4) TAP(21,5) TAP(22,6) TAP(23,7)
            TAP(24,8) TAP(25,9) TAP(26,10) TAP(27,11) TAP(28,12) TAP(29,13) TAP(30,14) TAP(31,15)
            STSFLUSH(2)
        }
        __syncthreads();

#pragma unroll
        for (int half = 0; half < 2; half++) {
            float acc[2][4][4];
#pragma unroll
            for (int a = 0; a < 2; a++)
#pragma unroll
                for (int b = 0; b < 4; b++)
#pragma unroll
                    for (int c = 0; c < 4; c++) acc[a][b][c] = 0.f;

            const int r0 = half * 128 + warp_m * 32 + (lane & 15);
            const int r1 = r0 + 16;
#pragma unroll
            for (int kk = 0; kk < 2; kk++) {
                const int chh = kk * 2 + khalf, chl = chh + 4;
                uint32_t ah0[4], ah1[4], al0[4], al1[4];
                ldsm4(ah0, sb + (uint32_t)r0 * 128 + ((chh ^ (r0 & 7)) << 4));
                ldsm4(ah1, sb + (uint32_t)r1 * 128 + ((chh ^ (r1 & 7)) << 4));
                ldsm4(al0, sb + (uint32_t)r0 * 128 + ((chl ^ (r0 & 7)) << 4));
                ldsm4(al1, sb + (uint32_t)r1 * 128 + ((chl ^ (r1 & 7)) << 4));

                const unsigned short* bs0 = wF + (((0 + kk) * 32 + lane) * 32 + warp_n * 16);
                const unsigned short* bs1 = wF + (((2 + kk) * 32 + lane) * 32 + warp_n * 16);
                uint4 h0 = *reinterpret_cast<const uint4*>(bs0);
                uint4 h1 = *reinterpret_cast<const uint4*>(bs0 + 8);
                uint4 l0 = *reinterpret_cast<const uint4*>(bs1);
                uint4 l1 = *reinterpret_cast<const uint4*>(bs1 + 8);
                uint32_t bh[8] = {h0.x, h0.y, h0.z, h0.w, h1.x, h1.y, h1.z, h1.w};
                uint32_t bl[8] = {l0.x, l0.y, l0.z, l0.w, l1.x, l1.y, l1.z, l1.w};

#pragma unroll
                for (int nb = 0; nb < 4; nb++) {
                    mma16816(acc[0][nb], ah0, bh[nb * 2], bh[nb * 2 + 1]);
                    mma16816(acc[1][nb], ah1, bh[nb * 2], bh[nb * 2 + 1]);
                }
#pragma unroll
                for (int nb = 0; nb < 4; nb++) {
                    mma16816(acc[0][nb], ah0, bl[nb * 2], bl[nb * 2 + 1]);
                    mma16816(acc[1][nb], ah1, bl[nb * 2], bl[nb * 2 + 1]);
                }
#pragma unroll
                for (int nb = 0; nb < 4; nb++) {
                    mma16816(acc[0][nb], al0, bh[nb * 2], bh[nb * 2 + 1]);
                    mma16816(acc[1][nb], al1, bh[nb * 2], bh[nb * 2 + 1]);
                }
            }

#pragma unroll
            for (int mb = 0; mb < 2; mb++) {
                const int rbase = it * 256 + half * 128 + warp_m * 32 + mb * 16;
#pragma unroll
                for (int nb = 0; nb < 4; nb++) {
                    float* d = acc[mb][nb];
                    s0[nb] += d[0] + d[2];
                    s1[nb] += d[1] + d[3];
                    q0[nb] += d[0] * d[0] + d[2] * d[2];
                    q1[nb] += d[1] * d[1] + d[3] * d[3];
                    float m0v = fmaxf(d[0], __shfl_xor_sync(0xffffffffu, d[0], 4));
                    float m1v = fmaxf(d[1], __shfl_xor_sync(0xffffffffu, d[1], 4));
                    float m2v = fmaxf(d[2], __shfl_xor_sync(0xffffffffu, d[2], 4));
                    float m3v = fmaxf(d[3], __shfl_xor_sync(0xffffffffu, d[3], 4));
                    if ((lane & 4) == 0) {
                        const int col = warp_n * 32 + nb * 8 + (lane & 3) * 2;
                        int P = rbase + (lane >> 2);
                        int y = P / 80, x2 = (P % 80) >> 1;
                        *reinterpret_cast<float2*>(xp + ((size_t)y * 40 + x2) * 64 + col) =
                            make_float2(m0v, m1v);
                        int P8 = P + 8;
                        int y8 = P8 / 80, x28 = (P8 % 80) >> 1;
                        *reinterpret_cast<float2*>(xp + ((size_t)y8 * 40 + x28) * 64 + col) =
                            make_float2(m2v, m3v);
                    }
                }
            }
        }
        __syncthreads();
    }
#undef TAP
#undef STSFLUSH
    stats_flush(0, n, lane, warp_n, s0, s1, q0, q1);
}

// ========= ypoolF: fused BN-finalize + y-pool + BN + LReLU -> bf16 hi/lo =========
template <int HO>
__global__ void ypoolF_k(const float* __restrict__ xp,
                         unsigned short* __restrict__ ohi, unsigned short* __restrict__ olo,
                         int statsBase, const float* __restrict__ gam, const float* __restrict__ bet) {
    __shared__ float s_sc[256], s_sh[256];
    {
        int t = threadIdx.x, grp = t >> 6, oc = t & 63;
        float cnt = (grp == 0 ? (float)NQ : 8.f) * (float)(4 * HO * HO);
        float m = g_stats[statsBase + t * 2] / cnt;
        float v = g_stats[statsBase + t * 2 + 1] / cnt - m * m;
        float sc = gam[oc] * rsqrtf(v + EPS_BN);
        s_sc[t] = sc;
        s_sh[t] = bet[oc] - m * sc;
    }
    __syncthreads();
    int idx = blockIdx.x * 256 + threadIdx.x;
    if (idx >= NTOT * HO * HO * 16) return;
    int c4 = idx & 15, t = idx >> 4;
    int px = t % HO; t /= HO;
    int py = t % HO;
    int n = t / HO, g = bn_group(n);
    float4 sc = *reinterpret_cast<const float4*>(&s_sc[g * 64 + c4 * 4]);
    float4 sh = *reinterpret_cast<const float4*>(&s_sh[g * 64 + c4 * 4]);
    const float* p = xp + (((size_t)n * (2 * HO) + 2 * py) * HO + px) * 64 + c4 * 4;
    float4 a = *reinterpret_cast<const float4*>(p);
    float4 b = *reinterpret_cast<const float4*>(p + HO * 64);
    float r[4];
    r[0] = bnlr(fmaxf(a.x, b.x), sc.x, sh.x);
    r[1] = bnlr(fmaxf(a.y, b.y), sc.y, sh.y);
    r[2] = bnlr(fmaxf(a.z, b.z), sc.z, sh.z);
    r[3] = bnlr(fmaxf(a.w, b.w), sc.w, sh.w);
    unsigned short h[4], l[4];
#pragma unroll
    for (int j = 0; j < 4; j++) {
        __nv_bfloat16 hb = __float2bfloat16(r[j]);
        h[j] = __bfloat16_as_ushort(hb);
        l[j] = __bfloat16_as_ushort(__float2bfloat16(r[j] - __bfloat162float(hb)));
    }
    size_t base = (((size_t)n * HO + py) * HO + px) * 64 + c4 * 4;
    *reinterpret_cast<uint2*>(ohi + base) = make_uint2((uint32_t)h[0] | ((uint32_t)h[1] << 16),
                                                       (uint32_t)h[2] | ((uint32_t)h[3] << 16));
    *reinterpret_cast<uint2*>(olo + base) = make_uint2((uint32_t)l[0] | ((uint32_t)l[1] << 16),
                                                       (uint32_t)l[2] | ((uint32_t)l[3] << 16));
}

// ======================= conv L2-L4 + stats slice ====================
template <int H>
__global__ void __launch_bounds__(256) conv_t(
    const unsigned short* __restrict__ inhi, const unsigned short* __restrict__ inlo,
    float* __restrict__ outbuf, const unsigned short* __restrict__ wBf, int statsBase)
{
    constexpr int NPIX = H * H, W2 = H + 2;
    constexpr int NT = (NPIX + 127) / 128;
    constexpr int RB = (127 + H - 1) / H + 3;
    constexpr int SLOTS = RB * W2;
    constexpr int BANDB = SLOTS * 128;
    extern __shared__ __align__(16) unsigned char smem[];
    const uint32_t sb = smem_u32(smem);
    const int tid = threadIdx.x, lane = tid & 31, wid = tid >> 5;
    const int warp_m = wid & 3, warp_n = wid >> 2;
    const int n = blockIdx.x;
    const unsigned short* ghi = inhi + (size_t)n * NPIX * 64;
    const unsigned short* glo = inlo + (size_t)n * NPIX * 64;
    float* gout;
    if constexpr (H == 10) gout = outbuf + (size_t)n * 64;
    else                   gout = outbuf + (size_t)n * (H * (H / 2) * 64);

    float s0[4] = {0,0,0,0}, s1[4] = {0,0,0,0}, q0[4] = {0,0,0,0}, q1[4] = {0,0,0,0};

    for (int t = 0; t < NT; t++) {
        __syncthreads();
        const int m0 = t * 128, ytile = m0 / H;
        for (int sl = tid; sl < SLOTS; sl += 256) {
            int r = sl / W2, c = sl - r * W2;
            int y = ytile + r - 1, x = c - 1;
            bool v = ((unsigned)y < (unsigned)H) && ((unsigned)x < (unsigned)H);
            const uint4* sh = reinterpret_cast<const uint4*>(ghi + (size_t)(y * H + x) * 64);
            const uint4* so = reinterpret_cast<const uint4*>(glo + (size_t)(y * H + x) * 64);
#pragma unroll
            for (int ch = 0; ch < 8; ch++) {
                uint4 dh = v ? sh[ch] : make_uint4(0, 0, 0, 0);
                uint4 dl = v ? so[ch] : make_uint4(0, 0, 0, 0);
                uint32_t off = (uint32_t)sl * 128 + (uint32_t)((ch ^ (sl & 7)) << 4);
                *reinterpret_cast<uint4*>(smem + off) = dh;
                *reinterpret_cast<uint4*>(smem + BANDB + off) = dl;
            }
        }
        __syncthreads();

        int bp[2];
#pragma unroll
        for (int mb = 0; mb < 2; mb++) {
            int p = m0 + warp_m * 32 + mb * 16 + (lane & 15);
            int y = p / H, x = p - y * H;
            bp[mb] = (y - ytile + 1) * W2 + x + 1;
        }
        const int khalf = lane >> 4;

        float acc[2][4][4];
#pragma unroll
        for (int a = 0; a < 2; a++)
#pragma unroll
            for (int b = 0; b < 4; b++)
#pragma unroll
                for (int c = 0; c < 4; c++) acc[a][b][c] = 0.f;

#pragma unroll 3
        for (int s = 0; s < 9; s++) {
            const int so9 = (s / 3 - 1) * W2 + (s % 3 - 1);
            const int b0 = bp[0] + so9, b1 = bp[1] + so9;
#pragma unroll
            for (int kk = 0; kk < 4; kk++) {
                const int ch = kk * 2 + khalf;
                uint32_t off0 = (uint32_t)b0 * 128 + (uint32_t)((ch ^ (b0 & 7)) << 4);
                uint32_t off1 = (uint32_t)b1 * 128 + (uint32_t)((ch ^ (b1 & 7)) << 4);
                uint32_t ah0[4], ah1[4], al0[4], al1[4];
                ldsm4(ah0, sb + off0);
                ldsm4(ah1, sb + off1);
                ldsm4(al0, sb + BANDB + off0);
                ldsm4(al1, sb + BANDB + off1);

                const unsigned short* bs0 = wBf + ((((s * 2 + 0) * 4 + kk) * 32 + lane) * 32 + warp_n * 16);
                const unsigned short* bs1 = wBf + ((((s * 2 + 1) * 4 + kk) * 32 + lane) * 32 + warp_n * 16);
                uint4 h0 = *reinterpret_cast<const uint4*>(bs0);
                uint4 h1 = *reinterpret_cast<const uint4*>(bs0 + 8);
                uint4 l0 = *reinterpret_cast<const uint4*>(bs1);
                uint4 l1 = *reinterpret_cast<const uint4*>(bs1 + 8);
                uint32_t bh[8] = {h0.x, h0.y, h0.z, h0.w, h1.x, h1.y, h1.z, h1.w};
                uint32_t bl[8] = {l0.x, l0.y, l0.z, l0.w, l1.x, l1.y, l1.z, l1.w};

#pragma unroll
                for (int nb = 0; nb < 4; nb++) {
                    mma16816(acc[0][nb], ah0, bh[nb * 2], bh[nb * 2 + 1]);
                    mma16816(acc[1][nb], ah1, bh[nb * 2], bh[nb * 2 + 1]);
                }
#pragma unroll
                for (int nb = 0; nb < 4; nb++) {
                    mma16816(acc[0][nb], ah0, bl[nb * 2], bl[nb * 2 + 1]);
                    mma16816(acc[1][nb], ah1, bl[nb * 2], bl[nb * 2 + 1]);
                }
#pragma unroll
                for (int nb = 0; nb < 4; nb++) {
                    mma16816(acc[0][nb], al0, bh[nb * 2], bh[nb * 2 + 1]);
                    mma16816(acc[1][nb], al1, bh[nb * 2], bh[nb * 2 + 1]);
                }
            }
        }

        if constexpr (H == 10) {
            float mx0[4], mx1[4];
#pragma unroll
            for (int nb = 0; nb < 4; nb++) { mx0[nb] = -1e30f; mx1[nb] = -1e30f; }
#pragma unroll
            for (int mb = 0; mb < 2; mb++) {
                int p0 = m0 + warp_m * 32 + mb * 16 + (lane >> 2);
                bool v0 = p0 < NPIX, v1 = (p0 + 8) < NPIX;
#pragma unroll
                for (int nb = 0; nb < 4; nb++) {
                    float* d = acc[mb][nb];
                    if (v0) {
                        s0[nb] += d[0]; s1[nb] += d[1];
                        q0[nb] += d[0] * d[0]; q1[nb] += d[1] * d[1];
                        mx0[nb] = fmaxf(mx0[nb], d[0]); mx1[nb] = fmaxf(mx1[nb], d[1]);
                    }
                    if (v1) {
                        s0[nb] += d[2]; s1[nb] += d[3];
                        q0[nb] += d[2] * d[2]; q1[nb] += d[3] * d[3];
                        mx0[nb] = fmaxf(mx0[nb], d[2]); mx1[nb] = fmaxf(mx1[nb], d[3]);
                    }
                }
            }
#pragma unroll
            for (int o = 4; o <= 16; o <<= 1)
#pragma unroll
                for (int nb = 0; nb < 4; nb++) {
                    mx0[nb] = fmaxf(mx0[nb], __shfl_xor_sync(0xffffffffu, mx0[nb], o));
                    mx1[nb] = fmaxf(mx1[nb], __shfl_xor_sync(0xffffffffu, mx1[nb], o));
                }
            __syncthreads();
            float* smax = (float*)smem;
            if (lane < 4) {
#pragma unroll
                for (int nb = 0; nb < 4; nb++) {
                    int col = warp_n * 32 + nb * 8 + lane * 2;
                    smax[warp_m * 64 + col]     = mx0[nb];
                    smax[warp_m * 64 + col + 1] = mx1[nb];
                }
            }
            __syncthreads();
            if (tid < 64)
                gout[tid] = fmaxf(fmaxf(smax[tid], smax[64 + tid]),
                                  fmaxf(smax[128 + tid], smax[192 + tid]));
        } else {
#pragma unroll
            for (int mb = 0; mb < 2; mb++) {
                int p0 = m0 + warp_m * 32 + mb * 16 + (lane >> 2);
                bool v0 = p0 < NPIX, v1 = (p0 + 8) < NPIX;
#pragma unroll
                for (int nb = 0; nb < 4; nb++) {
                    float* d = acc[mb][nb];
                    if (v0) { s0[nb] += d[0]; s1[nb] += d[1]; q0[nb] += d[0]*d[0]; q1[nb] += d[1]*d[1]; }
                    if (v1) { s0[nb] += d[2]; s1[nb] += d[3]; q0[nb] += d[2]*d[2]; q1[nb] += d[3]*d[3]; }
                    float m0v = fmaxf(d[0], __shfl_xor_sync(0xffffffffu, d[0], 4));
                    float m1v = fmaxf(d[1], __shfl_xor_sync(0xffffffffu, d[1], 4));
                    float m2v = fmaxf(d[2], __shfl_xor_sync(0xffffffffu, d[2], 4));
                    float m3v = fmaxf(d[3], __shfl_xor_sync(0xffffffffu, d[3], 4));
                    if ((lane & 4) == 0) {
                        int col = warp_n * 32 + nb * 8 + (lane & 3) * 2;
                        if (v0) {
                            int y = p0 / H, x2 = (p0 % H) >> 1;
                            *reinterpret_cast<float2*>(gout + ((size_t)y * (H / 2) + x2) * 64 + col) =
                                make_float2(m0v, m1v);
                        }
                        if (v1) {
                            int p8 = p0 + 8, y = p8 / H, x2 = (p8 % H) >> 1;
                            *reinterpret_cast<float2*>(gout + ((size_t)y * (H / 2) + x2) * 64 + col) =
                                make_float2(m2v, m3v);
                        }
                    }
                }
            }
        }
    }
    stats_flush(statsBase, n, lane, warp_n, s0, s1, q0, q1);
}

// embedF: fused finalize L4 + BN + LReLU over per-image channel max
__global__ void embedF_k(const float* __restrict__ mx,
                         const float* __restrict__ gam, const float* __restrict__ bet) {
    int idx = blockIdx.x * 256 + threadIdx.x;
    if (idx >= NTOT * 64) return;
    int c = idx & 63, n = idx >> 6, g = bn_group(n);
    float cnt = (g == 0 ? (float)NQ : 8.f) * 100.f;
    float m = g_stats[1536 + (g * 64 + c) * 2] / cnt;
    float v = g_stats[1536 + (g * 64 + c) * 2 + 1] / cnt - m * m;
    float sc = gam[c] * rsqrtf(v + EPS_BN);
    float sh = bet[c] - m * sc;
    g_emb[idx] = bnlr(mx[idx], sc, sh);
}

// ======================= attention over 3 prototypes =======================
__global__ void attn_k(const float* __restrict__ wq, const float* __restrict__ wk,
                       const float* __restrict__ wv, const float* __restrict__ fcw,
                       const float* __restrict__ fcb, const float* __restrict__ lng,
                       const float* __restrict__ lnb) {
    __shared__ float P[3][64], Q[3][64], K[3][64], V[3][64], O[3][64];
    __shared__ float A[3][3], MU[3], SG[3], NR[3];
    int t = threadIdx.x;
    for (int l = 0; l < 3; l++) {
        float s = 0.f;
        for (int i = 0; i < 8; i++) s += g_emb[(NQ + l * 8 + i) * 64 + t];
        P[l][t] = s * 0.125f;
    }
    __syncthreads();
    for (int l = 0; l < 3; l++) {
        float q = 0.f, k = 0.f, v = 0.f;
        for (int d = 0; d < 64; d++) {
            float p = P[l][d];
            q += p * wq[t * 64 + d]; k += p * wk[t * 64 + d]; v += p * wv[t * 64 + d];
        }
        Q[l][t] = q; K[l][t] = k; V[l][t] = v;
    }
    __syncthreads();
    if (t < 9) {
        int qi = t / 3, ki = t % 3;
        float a = 0.f;
        for (int d = 0; d < 64; d++) a += Q[qi][d] * K[ki][d];
        A[qi][ki] = a * 0.125f;
    }
    __syncthreads();
    if (t < 3) {
        float m = fmaxf(A[t][0], fmaxf(A[t][1], A[t][2]));
        float e0 = expf(A[t][0] - m), e1 = expf(A[t][1] - m), e2 = expf(A[t][2] - m);
        float inv = 1.f / (e0 + e1 + e2);
        A[t][0] = e0 * inv; A[t][1] = e1 * inv; A[t][2] = e2 * inv;
    }
    __syncthreads();
    for (int l = 0; l < 3; l++)
        O[l][t] = A[l][0] * V[0][t] + A[l][1] * V[1][t] + A[l][2] * V[2][t];
    __syncthreads();
    for (int l = 0; l < 3; l++) {
        float o = fcb[t];
        for (int d = 0; d < 64; d++) o += O[l][d] * fcw[t * 64 + d];
        Q[l][t] = o + P[l][t];
    }
    __syncthreads();
    if (t < 3) {
        float s = 0.f, q = 0.f;
        for (int d = 0; d < 64; d++) { float x = Q[t][d]; s += x; q += x * x; }
        float m = s / 64.f;
        MU[t] = m;
        SG[t] = rsqrtf(q / 64.f - m * m + EPS_LN);
    }
    __syncthreads();
    for (int l = 0; l < 3; l++)
        K[l][t] = (Q[l][t] - MU[l]) * SG[l] * lng[t] + lnb[t];
    __syncthreads();
    if (t < 3) {
        float q = 0.f;
        for (int d = 0; d < 64; d++) q += K[t][d] * K[t][d];
        NR[t] = rsqrtf(q);
    }
    __syncthreads();
    for (int l = 0; l < 3; l++) g_sn[l * 64 + t] = K[l][t] * NR[l];
}

__global__ void cos_k(float* __restrict__ out) {
    int warp = threadIdx.x >> 5, lane = threadIdx.x & 31;
    int n = blockIdx.x * 4 + warp;
    if (n >= NQ) return;
    float v1 = g_emb[n * 64 + lane], v2 = g_emb[n * 64 + 32 + lane];
    float ss = v1 * v1 + v2 * v2;
#pragma unroll
    for (int o = 16; o > 0; o >>= 1) ss += __shfl_xor_sync(0xffffffffu, ss, o);
    float rn = rsqrtf(ss);
#pragma unroll
    for (int k = 0; k < 3; k++) {
        float d = v1 * g_sn[k * 64 + lane] + v2 * g_sn[k * 64 + 32 + lane];
#pragma unroll
        for (int o = 16; o > 0; o >>= 1) d += __shfl_xor_sync(0xffffffffu, d, o);
        if (lane == 0) out[n * 3 + k] = d * rn;
    }
}

// ======================= launch =======================
extern "C" void kernel_launch(void* const* d_in, const int* in_sizes, int n_in,
                              void* d_out, int out_size) {
    const float* input1  = (const float*)d_in[0];
    const float* input2  = (const float*)d_in[1];
    const float* conv1_w = (const float*)d_in[2];
    const float* conv2_w = (const float*)d_in[3];
    const float* conv3_w = (const float*)d_in[4];
    const float* conv4_w = (const float*)d_in[5];
    const float* bn_g[4] = {(const float*)d_in[6], (const float*)d_in[8], (const float*)d_in[10], (const float*)d_in[12]};
    const float* bn_b[4] = {(const float*)d_in[7], (const float*)d_in[9], (const float*)d_in[11], (const float*)d_in[13]};
    float* out = (float*)d_out;

    const int DS1  = 32768 + 76800;       // 109568: 256-row A tile + raw image
    const int SM40 = 2 * 7 * 42 * 128;    // 75264
    const int SM20 = 2 * 10 * 22 * 128;   // 56320
    const int SM10 = 2 * 16 * 12 * 128;   // 49152
    cudaFuncSetAttribute(conv1_t,    cudaFuncAttributeMaxDynamicSharedMemorySize, DS1);
    cudaFuncSetAttribute(conv_t<40>, cudaFuncAttributeMaxDynamicSharedMemorySize, SM40);
    cudaFuncSetAttribute(conv_t<20>, cudaFuncAttributeMaxDynamicSharedMemorySize, SM20);
    cudaFuncSetAttribute(conv_t<10>, cudaFuncAttributeMaxDynamicSharedMemorySize, SM10);

    unsigned short *wF1, *wF2, *wF3, *wF4, *ihi, *ilo;
    cudaGetSymbolAddress((void**)&wF1, g_wF1);
    cudaGetSymbolAddress((void**)&wF2, g_wF2);
    cudaGetSymbolAddress((void**)&wF3, g_wF3);
    cudaGetSymbolAddress((void**)&wF4, g_wF4);
    cudaGetSymbolAddress((void**)&ihi, g_inhi);
    cudaGetSymbolAddress((void**)&ilo, g_inlo);
    float *c1, *c2, *c3, *c4;
    cudaGetSymbolAddress((void**)&c1, g_c1out);
    cudaGetSymbolAddress((void**)&c2, g_c2out);
    cudaGetSymbolAddress((void**)&c3, g_c3out);
    cudaGetSymbolAddress((void**)&c4, g_c4out);

    // Launch order: prep(1), conv1_t(2), ypoolF40(3), conv_t<40>(4 <- profiled)
    prep_k<<<dim3(72, 4), 256>>>(conv1_w, conv2_w, conv3_w, conv4_w);
    conv1_t<<<NTOT, 256, DS1>>>(input1, input2, wF1);
    ypoolF_k<40><<<(NTOT * 40 * 40 * 16 + 255) / 256, 256>>>(c1, ihi, ilo, 0, bn_g[0], bn_b[0]);
    conv_t<40><<<NTOT, 256, SM40>>>(ihi, ilo, c2, wF2, 512);
    ypoolF_k<20><<<(NTOT * 20 * 20 * 16 + 255) / 256, 256>>>(c2, ihi, ilo, 512, bn_g[1], bn_b[1]);
    conv_t<20><<<NTOT, 256, SM20>>>(ihi, ilo, c3, wF3, 1024);
    ypoolF_k<10><<<(NTOT * 10 * 10 * 16 + 255) / 256, 256>>>(c3, ihi, ilo, 1024, bn_g[2], bn_b[2]);
    conv_t<10><<<NTOT, 256, SM10>>>(ihi, ilo, c4, wF4, 1536);
    embedF_k<<<(NTOT * 64 + 255) / 256, 256>>>(c4, bn_g[3], bn_b[3]);

    attn_k<<<1, 64>>>((const float*)d_in[14], (const float*)d_in[15], (const float*)d_in[16],
                      (const float*)d_in[17], (const float*)d_in[18],
                      (const float*)d_in[19], (const float*)d_in[20]);
    cos_k<<<256, 128>>>(out);
}

// round 17
// speedup vs baseline: 1.1057x; 1.0536x over previous
#include <cuda_runtime.h>
#include <cuda_bf16.h>
#include <math.h>
#include <stdint.h>

#define EPS_BN 1e-5f
#define EPS_LN 1e-5f
#define NQ   1024
#define NTOT 1048

// ======================= helpers =======================
__device__ __forceinline__ uint32_t smem_u32(const void* p) {
    uint32_t a;
    asm("{ .reg .u64 t; cvta.to.shared.u64 t, %1; cvt.u32.u64 %0, t; }" : "=r"(a) : "l"(p));
    return a;
}
__device__ __forceinline__ void ldsm4(uint32_t* r, uint32_t addr) {
    asm volatile("ldmatrix.sync.aligned.m8n8.x4.shared.b16 {%0,%1,%2,%3}, [%4];"
                 : "=r"(r[0]), "=r"(r[1]), "=r"(r[2]), "=r"(r[3]) : "r"(addr) : "memory");
}
__device__ __forceinline__ void mma16816(float* d, const uint32_t* a, uint32_t b0, uint32_t b1) {
    asm volatile("mma.sync.aligned.m16n8k16.row.col.f32.bf16.bf16.f32 "
                 "{%0,%1,%2,%3}, {%4,%5,%6,%7}, {%8,%9}, {%0,%1,%2,%3};"
                 : "+f"(d[0]), "+f"(d[1]), "+f"(d[2]), "+f"(d[3])
                 : "r"(a[0]), "r"(a[1]), "r"(a[2]), "r"(a[3]), "r"(b0), "r"(b1));
}
__device__ __forceinline__ float bnlr(float x, float sc, float sh) {
    x = fmaf(x, sc, sh);
    return x > 0.f ? x : 0.2f * x;
}

// ======================= scratch (NHWC) =======================
static __device__ float g_c1out[429260800];   // xpool1 [1048][80][40][64]
static __device__ float g_c2out[107315200];   // xpool2 [1048][40][20][64]
static __device__ float g_c3out[26828800];    // xpool3 [1048][20][10][64]
static __device__ float g_c4out[6707200];     // maxraw [1048][64]
static __device__ unsigned short g_inhi[107315200];
static __device__ unsigned short g_inlo[107315200];
static __device__ float g_stats[2048];        // 4 layers x (group,oc) x {sum,sq}
static __device__ __align__(16) unsigned short g_wF1[4096];
static __device__ __align__(16) unsigned short g_wF2[73728];
static __device__ __align__(16) unsigned short g_wF3[73728];
static __device__ __align__(16) unsigned short g_wF4[73728];
static __device__ float g_emb[NTOT * 64];
static __device__ float g_sn[3 * 64];

__device__ __forceinline__ int bn_group(int n) { return (n < NQ) ? 0 : (1 + ((n - NQ) >> 3)); }

__device__ __forceinline__ void stats_flush(int base, int n, int lane, int warp_n,
                                            float* s0, float* s1, float* q0, float* q1) {
#pragma unroll
    for (int o = 4; o <= 16; o <<= 1) {
#pragma unroll
        for (int nb = 0; nb < 4; nb++) {
            s0[nb] += __shfl_down_sync(0xffffffffu, s0[nb], o);
            s1[nb] += __shfl_down_sync(0xffffffffu, s1[nb], o);
            q0[nb] += __shfl_down_sync(0xffffffffu, q0[nb], o);
            q1[nb] += __shfl_down_sync(0xffffffffu, q1[nb], o);
        }
    }
    if (lane < 4) {
        int g = bn_group(n);
#pragma unroll
        for (int nb = 0; nb < 4; nb++) {
            int c0 = warp_n * 32 + nb * 8 + lane * 2;
            atomicAdd(&g_stats[base + (g * 64 + c0) * 2],     s0[nb]);
            atomicAdd(&g_stats[base + (g * 64 + c0) * 2 + 1], q0[nb]);
            atomicAdd(&g_stats[base + (g * 64 + c0 + 1) * 2],     s1[nb]);
            atomicAdd(&g_stats[base + (g * 64 + c0 + 1) * 2 + 1], q1[nb]);
        }
    }
}

// ======================= launch 1: ALL weight prep + stats zero =======================
__global__ void prep_k(const float* __restrict__ w1, const float* __restrict__ w2,
                       const float* __restrict__ w3, const float* __restrict__ w4) {
    int y = blockIdx.y;
    int e = blockIdx.x * 256 + threadIdx.x;
    if (y == 0) {
        if (e < 2048) g_stats[e] = 0.f;
        if (e >= 1024) return;
        int nb = e & 7, lane = (e >> 3) & 31, kk = (e >> 8) & 1, cmb = (e >> 9) & 1;
        int n = nb * 8 + (lane >> 2);
#pragma unroll
        for (int j = 0; j < 2; j++)
#pragma unroll
            for (int h = 0; h < 2; h++) {
                int k = kk * 16 + (lane & 3) * 2 + j * 8 + h;
                float x = 0.f;
                if (k < 27) { int ic = k / 9, s = k - ic * 9; x = w1[(n * 3 + ic) * 9 + s]; }
                __nv_bfloat16 hi = __float2bfloat16(x);
                unsigned short v;
                if (cmb == 0) v = __bfloat16_as_ushort(hi);
                else          v = __bfloat16_as_ushort(__float2bfloat16(x - __bfloat162float(hi)));
                g_wF1[e * 4 + j * 2 + h] = v;
            }
    } else {
        if (e >= 18432) return;
        const float* w = (y == 1) ? w2 : (y == 2) ? w3 : w4;
        unsigned short* dst = (y == 1) ? g_wF2 : (y == 2) ? g_wF3 : g_wF4;
        int nb = e & 7, lane = (e >> 3) & 31, kk = (e >> 8) & 3, cmb = (e >> 10) & 1, s = e >> 11;
        int n = nb * 8 + (lane >> 2);
#pragma unroll
        for (int j = 0; j < 2; j++)
#pragma unroll
            for (int h = 0; h < 2; h++) {
                int k = kk * 16 + (lane & 3) * 2 + j * 8 + h;
                float x = w[(n * 64 + k) * 9 + s];
                __nv_bfloat16 hi = __float2bfloat16(x);
                unsigned short v;
                if (cmb == 0) v = __bfloat16_as_ushort(hi);
                else          v = __bfloat16_as_ushort(__float2bfloat16(x - __bfloat162float(hi)));
                dst[e * 4 + j * 2 + h] = v;
            }
    }
}

// ===== launch 2: L1 mma conv, SMEM image, M=256 tile (2 halves per sync pair) =====
__global__ void __launch_bounds__(256, 2) conv1_t(
    const float* __restrict__ in1, const float* __restrict__ in2,
    const unsigned short* __restrict__ wF)
{
    constexpr int H = 80, NT2 = 25;               // 25 iterations x 256 px
    extern __shared__ __align__(16) unsigned char dsm[];
    unsigned char* sA = dsm;                      // 32768 B: 256 rows x 128 B
    float* sraw = (float*)(dsm + 32768);          // 19200 floats
    const uint32_t sb = smem_u32(sA);
    const int tid = threadIdx.x, lane = tid & 31, wid = tid >> 5;
    const int warp_m = wid & 3, warp_n = wid >> 2;
    const int khalf = lane >> 4;
    const int n = blockIdx.x;
    const float* gin = (n < NQ) ? in1 + (size_t)n * 19200 : in2 + (size_t)(n - NQ) * 19200;
    float* xp = g_c1out + (size_t)n * (80 * 40 * 64);

    for (int i = tid; i < 4800; i += 256)
        reinterpret_cast<float4*>(sraw)[i] = reinterpret_cast<const float4*>(gin)[i];

    float s0[4] = {0,0,0,0}, s1[4] = {0,0,0,0}, q0[4] = {0,0,0,0}, q1[4] = {0,0,0,0};
    uint32_t hp[8], lp[8];
    __syncthreads();

#define TAP(k, j) { \
    float val = 0.f; \
    if ((k) < 27) { \
        constexpr int ic = (k) / 9, s9 = (k) - ic * 9; \
        constexpr int dy = s9 / 3 - 1, dx = s9 % 3 - 1; \
        int yy = y + dy, xx = x + dx; \
        if ((unsigned)yy < (unsigned)H && (unsigned)xx < (unsigned)H) \
            val = sraw[ic * 6400 + yy * H + xx]; \
    } \
    __nv_bfloat16 hb = __float2bfloat16(val); \
    uint32_t hv = __bfloat16_as_ushort(hb); \
    uint32_t lv = __bfloat16_as_ushort(__float2bfloat16(val - __bfloat162float(hb))); \
    if (((j) & 1) == 0) { hp[(j) >> 1] = hv; lp[(j) >> 1] = lv; } \
    else { hp[(j) >> 1] |= hv << 16; lp[(j) >> 1] |= lv << 16; } }

#define STSFLUSH(c0) { \
    const uint32_t row = (uint32_t)tid * 128; \
    const uint32_t sw = (uint32_t)(tid & 7); \
    *reinterpret_cast<uint4*>(sA + row + ((((c0)    ) ^ sw) << 4)) = make_uint4(hp[0], hp[1], hp[2], hp[3]); \
    *reinterpret_cast<uint4*>(sA + row + ((((c0) + 1) ^ sw) << 4)) = make_uint4(hp[4], hp[5], hp[6], hp[7]); \
    *reinterpret_cast<uint4*>(sA + row + ((((c0) + 4) ^ sw) << 4)) = make_uint4(lp[0], lp[1], lp[2], lp[3]); \
    *reinterpret_cast<uint4*>(sA + row + ((((c0) + 5) ^ sw) << 4)) = make_uint4(lp[4], lp[5], lp[6], lp[7]); }

    for (int it = 0; it < NT2; it++) {
        {
            int P = it * 256 + tid;
            int y = P / H, x = P - (P / H) * H;
            TAP(0,0) TAP(1,1) TAP(2,2) TAP(3,3) TAP(4,4) TAP(5,5) TAP(6,6) TAP(7,7)
            TAP(8,8) TAP(9,9) TAP(10,10) TAP(11,11) TAP(12,12) TAP(13,13) TAP(14,14) TAP(15,15)
            STSFLUSH(0)
            TAP(16,0) TAP(17,1) TAP(18,2) TAP(19,3) TAP(20,4) TAP(21,5) TAP(22,6) TAP(23,7)
            TAP(24,8) TAP(25,9) TAP(26,10) TAP(27,11) TAP(28,12) TAP(29,13) TAP(30,14) TAP(31,15)
            STSFLUSH(2)
        }
        __syncthreads();

#pragma unroll
        for (int half = 0; half < 2; half++) {
            float acc[2][4][4];
#pragma unroll
            for (int a = 0; a < 2; a++)
#pragma unroll
                for (int b = 0; b < 4; b++)
#pragma unroll
                    for (int c = 0; c < 4; c++) acc[a][b][c] = 0.f;

            const int r0 = half * 128 + warp_m * 32 + (lane & 15);
            const int r1 = r0 + 16;
#pragma unroll
            for (int kk = 0; kk < 2; kk++) {
                const int chh = kk * 2 + khalf, chl = chh + 4;
                uint32_t ah0[4], ah1[4], al0[4], al1[4];
                ldsm4(ah0, sb + (uint32_t)r0 * 128 + ((chh ^ (r0 & 7)) << 4));
                ldsm4(ah1, sb + (uint32_t)r1 * 128 + ((chh ^ (r1 & 7)) << 4));
                ldsm4(al0, sb + (uint32_t)r0 * 128 + ((chl ^ (r0 & 7)) << 4));
                ldsm4(al1, sb + (uint32_t)r1 * 128 + ((chl ^ (r1 & 7)) << 4));

                const unsigned short* bs0 = wF + (((0 + kk) * 32 + lane) * 32 + warp_n * 16);
                const unsigned short* bs1 = wF + (((2 + kk) * 32 + lane) * 32 + warp_n * 16);
                uint4 h0 = *reinterpret_cast<const uint4*>(bs0);
                uint4 h1 = *reinterpret_cast<const uint4*>(bs0 + 8);
                uint4 l0 = *reinterpret_cast<const uint4*>(bs1);
                uint4 l1 = *reinterpret_cast<const uint4*>(bs1 + 8);
                uint32_t bh[8] = {h0.x, h0.y, h0.z, h0.w, h1.x, h1.y, h1.z, h1.w};
                uint32_t bl[8] = {l0.x, l0.y, l0.z, l0.w, l1.x, l1.y, l1.z, l1.w};

#pragma unroll
                for (int nb = 0; nb < 4; nb++) {
                    mma16816(acc[0][nb], ah0, bh[nb * 2], bh[nb * 2 + 1]);
                    mma16816(acc[1][nb], ah1, bh[nb * 2], bh[nb * 2 + 1]);
                }
#pragma unroll
                for (int nb = 0; nb < 4; nb++) {
                    mma16816(acc[0][nb], ah0, bl[nb * 2], bl[nb * 2 + 1]);
                    mma16816(acc[1][nb], ah1, bl[nb * 2], bl[nb * 2 + 1]);
                }
#pragma unroll
                for (int nb = 0; nb < 4; nb++) {
                    mma16816(acc[0][nb], al0, bh[nb * 2], bh[nb * 2 + 1]);
                    mma16816(acc[1][nb], al1, bh[nb * 2], bh[nb * 2 + 1]);
                }
            }

#pragma unroll
            for (int mb = 0; mb < 2; mb++) {
                const int rbase = it * 256 + half * 128 + warp_m * 32 + mb * 16;
#pragma unroll
                for (int nb = 0; nb < 4; nb++) {
                    float* d = acc[mb][nb];
                    s0[nb] += d[0] + d[2];
                    s1[nb] += d[1] + d[3];
                    q0[nb] += d[0] * d[0] + d[2] * d[2];
                    q1[nb] += d[1] * d[1] + d[3] * d[3];
                    float m0v = fmaxf(d[0], __shfl_xor_sync(0xffffffffu, d[0], 4));
                    float m1v = fmaxf(d[1], __shfl_xor_sync(0xffffffffu, d[1], 4));
                    float m2v = fmaxf(d[2], __shfl_xor_sync(0xffffffffu, d[2], 4));
                    float m3v = fmaxf(d[3], __shfl_xor_sync(0xffffffffu, d[3], 4));
                    if ((lane & 4) == 0) {
                        const int col = warp_n * 32 + nb * 8 + (lane & 3) * 2;
                        int P = rbase + (lane >> 2);
                        int y = P / 80, x2 = (P % 80) >> 1;
                        *reinterpret_cast<float2*>(xp + ((size_t)y * 40 + x2) * 64 + col) =
                            make_float2(m0v, m1v);
                        int P8 = P + 8;
                        int y8 = P8 / 80, x28 = (P8 % 80) >> 1;
                        *reinterpret_cast<float2*>(xp + ((size_t)y8 * 40 + x28) * 64 + col) =
                            make_float2(m2v, m3v);
                    }
                }
            }
        }
        __syncthreads();
    }
#undef TAP
#undef STSFLUSH
    stats_flush(0, n, lane, warp_n, s0, s1, q0, q1);
}

// ========= ypoolF: fused BN-finalize + y-pool + BN + LReLU -> bf16 hi/lo =========
template <int HO>
__global__ void ypoolF_k(const float* __restrict__ xp,
                         unsigned short* __restrict__ ohi, unsigned short* __restrict__ olo,
                         int statsBase, const float* __restrict__ gam, const float* __restrict__ bet) {
    __shared__ float s_sc[256], s_sh[256];
    {
        int t = threadIdx.x, grp = t >> 6, oc = t & 63;
        float cnt = (grp == 0 ? (float)NQ : 8.f) * (float)(4 * HO * HO);
        float m = g_stats[statsBase + t * 2] / cnt;
        float v = g_stats[statsBase + t * 2 + 1] / cnt - m * m;
        float sc = gam[oc] * rsqrtf(v + EPS_BN);
        s_sc[t] = sc;
        s_sh[t] = bet[oc] - m * sc;
    }
    __syncthreads();
    int idx = blockIdx.x * 256 + threadIdx.x;
    if (idx >= NTOT * HO * HO * 16) return;
    int c4 = idx & 15, t = idx >> 4;
    int px = t % HO; t /= HO;
    int py = t % HO;
    int n = t / HO, g = bn_group(n);
    float4 sc = *reinterpret_cast<const float4*>(&s_sc[g * 64 + c4 * 4]);
    float4 sh = *reinterpret_cast<const float4*>(&s_sh[g * 64 + c4 * 4]);
    const float* p = xp + (((size_t)n * (2 * HO) + 2 * py) * HO + px) * 64 + c4 * 4;
    float4 a = *reinterpret_cast<const float4*>(p);
    float4 b = *reinterpret_cast<const float4*>(p + HO * 64);
    float r[4];
    r[0] = bnlr(fmaxf(a.x, b.x), sc.x, sh.x);
    r[1] = bnlr(fmaxf(a.y, b.y), sc.y, sh.y);
    r[2] = bnlr(fmaxf(a.z, b.z), sc.z, sh.z);
    r[3] = bnlr(fmaxf(a.w, b.w), sc.w, sh.w);
    unsigned short h[4], l[4];
#pragma unroll
    for (int j = 0; j < 4; j++) {
        __nv_bfloat16 hb = __float2bfloat16(r[j]);
        h[j] = __bfloat16_as_ushort(hb);
        l[j] = __bfloat16_as_ushort(__float2bfloat16(r[j] - __bfloat162float(hb)));
    }
    size_t base = (((size_t)n * HO + py) * HO + px) * 64 + c4 * 4;
    *reinterpret_cast<uint2*>(ohi + base) = make_uint2((uint32_t)h[0] | ((uint32_t)h[1] << 16),
                                                       (uint32_t)h[2] | ((uint32_t)h[3] << 16));
    *reinterpret_cast<uint2*>(olo + base) = make_uint2((uint32_t)l[0] | ((uint32_t)l[1] << 16),
                                                       (uint32_t)l[2] | ((uint32_t)l[3] << 16));
}

// ============== conv L2-L4: M=256 tiles for H>=20 (fewer syncs, less band overread) ==
template <int H>
__global__ void __launch_bounds__(256) conv_t(
    const unsigned short* __restrict__ inhi, const unsigned short* __restrict__ inlo,
    float* __restrict__ outbuf, const unsigned short* __restrict__ wBf, int statsBase)
{
    constexpr int MT = (H >= 20) ? 256 : 128;
    constexpr int NHALF = MT / 128;
    constexpr int NPIX = H * H, W2 = H + 2;
    constexpr int NT = (NPIX + MT - 1) / MT;
    constexpr int RB = (MT - 1 + H - 1) / H + 3;
    constexpr int SLOTS = RB * W2;
    constexpr int BANDB = SLOTS * 128;
    extern __shared__ __align__(16) unsigned char smem[];
    const uint32_t sb = smem_u32(smem);
    const int tid = threadIdx.x, lane = tid & 31, wid = tid >> 5;
    const int warp_m = wid & 3, warp_n = wid >> 2;
    const int khalf = lane >> 4;
    const int n = blockIdx.x;
    const unsigned short* ghi = inhi + (size_t)n * NPIX * 64;
    const unsigned short* glo = inlo + (size_t)n * NPIX * 64;
    float* gout;
    if constexpr (H == 10) gout = outbuf + (size_t)n * 64;
    else                   gout = outbuf + (size_t)n * (H * (H / 2) * 64);

    float s0[4] = {0,0,0,0}, s1[4] = {0,0,0,0}, q0[4] = {0,0,0,0}, q1[4] = {0,0,0,0};

    for (int t = 0; t < NT; t++) {
        __syncthreads();
        const int m0 = t * MT, ytile = m0 / H;
        for (int sl = tid; sl < SLOTS; sl += 256) {
            int r = sl / W2, c = sl - r * W2;
            int y = ytile + r - 1, x = c - 1;
            bool v = ((unsigned)y < (unsigned)H) && ((unsigned)x < (unsigned)H);
            const uint4* sh = reinterpret_cast<const uint4*>(ghi + (size_t)(y * H + x) * 64);
            const uint4* so = reinterpret_cast<const uint4*>(glo + (size_t)(y * H + x) * 64);
#pragma unroll
            for (int ch = 0; ch < 8; ch++) {
                uint4 dh = v ? sh[ch] : make_uint4(0, 0, 0, 0);
                uint4 dl = v ? so[ch] : make_uint4(0, 0, 0, 0);
                uint32_t off = (uint32_t)sl * 128 + (uint32_t)((ch ^ (sl & 7)) << 4);
                *reinterpret_cast<uint4*>(smem + off) = dh;
                *reinterpret_cast<uint4*>(smem + BANDB + off) = dl;
            }
        }
        __syncthreads();

#pragma unroll 1
        for (int half = 0; half < NHALF; half++) {
            const int mh = m0 + half * 128;
            int bp[2];
#pragma unroll
            for (int mb = 0; mb < 2; mb++) {
                int p = mh + warp_m * 32 + mb * 16 + (lane & 15);
                int y = p / H, x = p - y * H;
                bp[mb] = (y - ytile + 1) * W2 + x + 1;
            }

            float acc[2][4][4];
#pragma unroll
            for (int a = 0; a < 2; a++)
#pragma unroll
                for (int b = 0; b < 4; b++)
#pragma unroll
                    for (int c = 0; c < 4; c++) acc[a][b][c] = 0.f;

#pragma unroll 3
            for (int s = 0; s < 9; s++) {
                const int so9 = (s / 3 - 1) * W2 + (s % 3 - 1);
                const int b0 = bp[0] + so9, b1 = bp[1] + so9;
#pragma unroll
                for (int kk = 0; kk < 4; kk++) {
                    const int ch = kk * 2 + khalf;
                    uint32_t off0 = (uint32_t)b0 * 128 + (uint32_t)((ch ^ (b0 & 7)) << 4);
                    uint32_t off1 = (uint32_t)b1 * 128 + (uint32_t)((ch ^ (b1 & 7)) << 4);
                    uint32_t ah0[4], ah1[4], al0[4], al1[4];
                    ldsm4(ah0, sb + off0);
                    ldsm4(ah1, sb + off1);
                    ldsm4(al0, sb + BANDB + off0);
                    ldsm4(al1, sb + BANDB + off1);

                    const unsigned short* bs0 = wBf + ((((s * 2 + 0) * 4 + kk) * 32 + lane) * 32 + warp_n * 16);
                    const unsigned short* bs1 = wBf + ((((s * 2 + 1) * 4 + kk) * 32 + lane) * 32 + warp_n * 16);
                    uint4 h0 = *reinterpret_cast<const uint4*>(bs0);
                    uint4 h1 = *reinterpret_cast<const uint4*>(bs0 + 8);
                    uint4 l0 = *reinterpret_cast<const uint4*>(bs1);
                    uint4 l1 = *reinterpret_cast<const uint4*>(bs1 + 8);
                    uint32_t bh[8] = {h0.x, h0.y, h0.z, h0.w, h1.x, h1.y, h1.z, h1.w};
                    uint32_t bl[8] = {l0.x, l0.y, l0.z, l0.w, l1.x, l1.y, l1.z, l1.w};

#pragma unroll
                    for (int nb = 0; nb < 4; nb++) {
                        mma16816(acc[0][nb], ah0, bh[nb * 2], bh[nb * 2 + 1]);
                        mma16816(acc[1][nb], ah1, bh[nb * 2], bh[nb * 2 + 1]);
                    }
#pragma unroll
                    for (int nb = 0; nb < 4; nb++) {
                        mma16816(acc[0][nb], ah0, bl[nb * 2], bl[nb * 2 + 1]);
                        mma16816(acc[1][nb], ah1, bl[nb * 2], bl[nb * 2 + 1]);
                    }
#pragma unroll
                    for (int nb = 0; nb < 4; nb++) {
                        mma16816(acc[0][nb], al0, bh[nb * 2], bh[nb * 2 + 1]);
                        mma16816(acc[1][nb], al1, bh[nb * 2], bh[nb * 2 + 1]);
                    }
                }
            }

            if constexpr (H == 10) {
                float mx0[4], mx1[4];
#pragma unroll
                for (int nb = 0; nb < 4; nb++) { mx0[nb] = -1e30f; mx1[nb] = -1e30f; }
#pragma unroll
                for (int mb = 0; mb < 2; mb++) {
                    int p0 = mh + warp_m * 32 + mb * 16 + (lane >> 2);
                    bool v0 = p0 < NPIX, v1 = (p0 + 8) < NPIX;
#pragma unroll
                    for (int nb = 0; nb < 4; nb++) {
                        float* d = acc[mb][nb];
                        if (v0) {
                            s0[nb] += d[0]; s1[nb] += d[1];
                            q0[nb] += d[0] * d[0]; q1[nb] += d[1] * d[1];
                            mx0[nb] = fmaxf(mx0[nb], d[0]); mx1[nb] = fmaxf(mx1[nb], d[1]);
                        }
                        if (v1) {
                            s0[nb] += d[2]; s1[nb] += d[3];
                            q0[nb] += d[2] * d[2]; q1[nb] += d[3] * d[3];
                            mx0[nb] = fmaxf(mx0[nb], d[2]); mx1[nb] = fmaxf(mx1[nb], d[3]);
                        }
                    }
                }
#pragma unroll
                for (int o = 4; o <= 16; o <<= 1)
#pragma unroll
                    for (int nb = 0; nb < 4; nb++) {
                        mx0[nb] = fmaxf(mx0[nb], __shfl_xor_sync(0xffffffffu, mx0[nb], o));
                        mx1[nb] = fmaxf(mx1[nb], __shfl_xor_sync(0xffffffffu, mx1[nb], o));
                    }
                __syncthreads();
                float* smax = (float*)smem;
                if (lane < 4) {
#pragma unroll
                    for (int nb = 0; nb < 4; nb++) {
                        int col = warp_n * 32 + nb * 8 + lane * 2;
                        smax[warp_m * 64 + col]     = mx0[nb];
                        smax[warp_m * 64 + col + 1] = mx1[nb];
                    }
                }
                __syncthreads();
                if (tid < 64)
                    gout[tid] = fmaxf(fmaxf(smax[tid], smax[64 + tid]),
                                      fmaxf(smax[128 + tid], smax[192 + tid]));
            } else {
#pragma unroll
                for (int mb = 0; mb < 2; mb++) {
                    int p0 = mh + warp_m * 32 + mb * 16 + (lane >> 2);
                    bool v0 = p0 < NPIX, v1 = (p0 + 8) < NPIX;
#pragma unroll
                    for (int nb = 0; nb < 4; nb++) {
                        float* d = acc[mb][nb];
                        if (v0) { s0[nb] += d[0]; s1[nb] += d[1]; q0[nb] += d[0]*d[0]; q1[nb] += d[1]*d[1]; }
                        if (v1) { s0[nb] += d[2]; s1[nb] += d[3]; q0[nb] += d[2]*d[2]; q1[nb] += d[3]*d[3]; }
                        float m0v = fmaxf(d[0], __shfl_xor_sync(0xffffffffu, d[0], 4));
                        float m1v = fmaxf(d[1], __shfl_xor_sync(0xffffffffu, d[1], 4));
                        float m2v = fmaxf(d[2], __shfl_xor_sync(0xffffffffu, d[2], 4));
                        float m3v = fmaxf(d[3], __shfl_xor_sync(0xffffffffu, d[3], 4));
                        if ((lane & 4) == 0) {
                            int col = warp_n * 32 + nb * 8 + (lane & 3) * 2;
                            if (v0) {
                                int y = p0 / H, x2 = (p0 % H) >> 1;
                                *reinterpret_cast<float2*>(gout + ((size_t)y * (H / 2) + x2) * 64 + col) =
                                    make_float2(m0v, m1v);
                            }
                            if (v1) {
                                int p8 = p0 + 8, y = p8 / H, x2 = (p8 % H) >> 1;
                                *reinterpret_cast<float2*>(gout + ((size_t)y * (H / 2) + x2) * 64 + col) =
                                    make_float2(m2v, m3v);
                            }
                        }
                    }
                }
            }
        }
    }
    stats_flush(statsBase, n, lane, warp_n, s0, s1, q0, q1);
}

// embedF: fused finalize L4 + BN + LReLU over per-image channel max
__global__ void embedF_k(const float* __restrict__ mx,
                         const float* __restrict__ gam, const float* __restrict__ bet) {
    int idx = blockIdx.x * 256 + threadIdx.x;
    if (idx >= NTOT * 64) return;
    int c = idx & 63, n = idx >> 6, g = bn_group(n);
    float cnt = (g == 0 ? (float)NQ : 8.f) * 100.f;
    float m = g_stats[1536 + (g * 64 + c) * 2] / cnt;
    float v = g_stats[1536 + (g * 64 + c) * 2 + 1] / cnt - m * m;
    float sc = gam[c] * rsqrtf(v + EPS_BN);
    float sh = bet[c] - m * sc;
    g_emb[idx] = bnlr(mx[idx], sc, sh);
}

// ======================= attention over 3 prototypes =======================
__global__ void attn_k(const float* __restrict__ wq, const float* __restrict__ wk,
                       const float* __restrict__ wv, const float* __restrict__ fcw,
                       const float* __restrict__ fcb, const float* __restrict__ lng,
                       const float* __restrict__ lnb) {
    __shared__ float P[3][64], Q[3][64], K[3][64], V[3][64], O[3][64];
    __shared__ float A[3][3], MU[3], SG[3], NR[3];
    int t = threadIdx.x;
    for (int l = 0; l < 3; l++) {
        float s = 0.f;
        for (int i = 0; i < 8; i++) s += g_emb[(NQ + l * 8 + i) * 64 + t];
        P[l][t] = s * 0.125f;
    }
    __syncthreads();
    for (int l = 0; l < 3; l++) {
        float q = 0.f, k = 0.f, v = 0.f;
        for (int d = 0; d < 64; d++) {
            float p = P[l][d];
            q += p * wq[t * 64 + d]; k += p * wk[t * 64 + d]; v += p * wv[t * 64 + d];
        }
        Q[l][t] = q; K[l][t] = k; V[l][t] = v;
    }
    __syncthreads();
    if (t < 9) {
        int qi = t / 3, ki = t % 3;
        float a = 0.f;
        for (int d = 0; d < 64; d++) a += Q[qi][d] * K[ki][d];
        A[qi][ki] = a * 0.125f;
    }
    __syncthreads();
    if (t < 3) {
        float m = fmaxf(A[t][0], fmaxf(A[t][1], A[t][2]));
        float e0 = expf(A[t][0] - m), e1 = expf(A[t][1] - m), e2 = expf(A[t][2] - m);
        float inv = 1.f / (e0 + e1 + e2);
        A[t][0] = e0 * inv; A[t][1] = e1 * inv; A[t][2] = e2 * inv;
    }
    __syncthreads();
    for (int l = 0; l < 3; l++)
        O[l][t] = A[l][0] * V[0][t] + A[l][1] * V[1][t] + A[l][2] * V[2][t];
    __syncthreads();
    for (int l = 0; l < 3; l++) {
        float o = fcb[t];
        for (int d = 0; d < 64; d++) o += O[l][d] * fcw[t * 64 + d];
        Q[l][t] = o + P[l][t];
    }
    __syncthreads();
    if (t < 3) {
        float s = 0.f, q = 0.f;
        for (int d = 0; d < 64; d++) { float x = Q[t][d]; s += x; q += x * x; }
        float m = s / 64.f;
        MU[t] = m;
        SG[t] = rsqrtf(q / 64.f - m * m + EPS_LN);
    }
    __syncthreads();
    for (int l = 0; l < 3; l++)
        K[l][t] = (Q[l][t] - MU[l]) * SG[l] * lng[t] + lnb[t];
    __syncthreads();
    if (t < 3) {
        float q = 0.f;
        for (int d = 0; d < 64; d++) q += K[t][d] * K[t][d];
        NR[t] = rsqrtf(q);
    }
    __syncthreads();
    for (int l = 0; l < 3; l++) g_sn[l * 64 + t] = K[l][t] * NR[l];
}

__global__ void cos_k(float* __restrict__ out) {
    int warp = threadIdx.x >> 5, lane = threadIdx.x & 31;
    int n = blockIdx.x * 4 + warp;
    if (n >= NQ) return;
    float v1 = g_emb[n * 64 + lane], v2 = g_emb[n * 64 + 32 + lane];
    float ss = v1 * v1 + v2 * v2;
#pragma unroll
    for (int o = 16; o > 0; o >>= 1) ss += __shfl_xor_sync(0xffffffffu, ss, o);
    float rn = rsqrtf(ss);
#pragma unroll
    for (int k = 0; k < 3; k++) {
        float d = v1 * g_sn[k * 64 + lane] + v2 * g_sn[k * 64 + 32 + lane];
#pragma unroll
        for (int o = 16; o > 0; o >>= 1) d += __shfl_xor_sync(0xffffffffu, d, o);
        if (lane == 0) out[n * 3 + k] = d * rn;
    }
}

// ======================= launch =======================
extern "C" void kernel_launch(void* const* d_in, const int* in_sizes, int n_in,
                              void* d_out, int out_size) {
    const float* input1  = (const float*)d_in[0];
    const float* input2  = (const float*)d_in[1];
    const float* conv1_w = (const float*)d_in[2];
    const float* conv2_w = (const float*)d_in[3];
    const float* conv3_w = (const float*)d_in[4];
    const float* conv4_w = (const float*)d_in[5];
    const float* bn_g[4] = {(const float*)d_in[6], (const float*)d_in[8], (const float*)d_in[10], (const float*)d_in[12]};
    const float* bn_b[4] = {(const float*)d_in[7], (const float*)d_in[9], (const float*)d_in[11], (const float*)d_in[13]};
    float* out = (float*)d_out;

    const int DS1  = 32768 + 76800;       // 109568
    const int SM40 = 2 * 10 * 42 * 128;   // 107520 (RB=10, MT=256)
    const int SM20 = 2 * 16 * 22 * 128;   // 90112  (RB=16, MT=256)
    const int SM10 = 2 * 16 * 12 * 128;   // 49152  (RB=16, MT=128)
    cudaFuncSetAttribute(conv1_t,    cudaFuncAttributeMaxDynamicSharedMemorySize, DS1);
    cudaFuncSetAttribute(conv_t<40>, cudaFuncAttributeMaxDynamicSharedMemorySize, SM40);
    cudaFuncSetAttribute(conv_t<20>, cudaFuncAttributeMaxDynamicSharedMemorySize, SM20);
    cudaFuncSetAttribute(conv_t<10>, cudaFuncAttributeMaxDynamicSharedMemorySize, SM10);

    unsigned short *wF1, *wF2, *wF3, *wF4, *ihi, *ilo;
    cudaGetSymbolAddress((void**)&wF1, g_wF1);
    cudaGetSymbolAddress((void**)&wF2, g_wF2);
    cudaGetSymbolAddress((void**)&wF3, g_wF3);
    cudaGetSymbolAddress((void**)&wF4, g_wF4);
    cudaGetSymbolAddress((void**)&ihi, g_inhi);
    cudaGetSymbolAddress((void**)&ilo, g_inlo);
    float *c1, *c2, *c3, *c4;
    cudaGetSymbolAddress((void**)&c1, g_c1out);
    cudaGetSymbolAddress((void**)&c2, g_c2out);
    cudaGetSymbolAddress((void**)&c3, g_c3out);
    cudaGetSymbolAddress((void**)&c4, g_c4out);

    // Launch order: prep(1), conv1_t(2), ypoolF40(3), conv_t<40>(4 <- profiled)
    prep_k<<<dim3(72, 4), 256>>>(conv1_w, conv2_w, conv3_w, conv4_w);
    conv1_t<<<NTOT, 256, DS1>>>(input1, input2, wF1);
    ypoolF_k<40><<<(NTOT * 40 * 40 * 16 + 255) / 256, 256>>>(c1, ihi, ilo, 0, bn_g[0], bn_b[0]);
    conv_t<40><<<NTOT, 256, SM40>>>(ihi, ilo, c2, wF2, 512);
    ypoolF_k<20><<<(NTOT * 20 * 20 * 16 + 255) / 256, 256>>>(c2, ihi, ilo, 512, bn_g[1], bn_b[1]);
    conv_t<20><<<NTOT, 256, SM20>>>(ihi, ilo, c3, wF3, 1024);
    ypoolF_k<10><<<(NTOT * 10 * 10 * 16 + 255) / 256, 256>>>(c3, ihi, ilo, 1024, bn_g[2], bn_b[2]);
    conv_t<10><<<NTOT, 256, SM10>>>(ihi, ilo, c4, wF4, 1536);
    embedF_k<<<(NTOT * 64 + 255) / 256, 256>>>(c4, bn_g[3], bn_b[3]);

    attn_k<<<1, 64>>>((const float*)d_in[14], (const float*)d_in[15], (const float*)d_in[16],
                      (const float*)d_in[17], (const float*)d_in[18],
                      (const float*)d_in[19], (const float*)d_in[20]);
    cos_k<<<256, 128>>>(out);
}